// round 7
// baseline (speedup 1.0000x reference)
#include <cuda_runtime.h>
#include <cstdint>

typedef unsigned long long u64;
typedef unsigned int u32;

// ---------------- problem constants ----------------
#define NA 9
#define HWPIX 65536
#define TOT 589824
#define PRE 6000
#define POST 300
#define NMS_T 0.7f
#define NWORDS 94
#define WPITCH 96
#define CAPBIG 16384
#define CAPB_LOOSE 12000
#define SORTN 8192
#define NBINS 65536
#define NTHR 1024

// ---------------- scratch ----------------
__device__ u32 g_barcnt;                 // monotonic across replays
__device__ u32 g_hist1[NBINS];           // all scores
__device__ u32 g_histv[NBINS];           // valid candidates >= T_loose
__device__ u32 g_hist2[NBINS];           // low 16 bits at boundary bin
__device__ int g_Tloose;
__device__ int g_T1;
__device__ u32 g_above;
__device__ int g_fb;
__device__ u64 g_thr64;
__device__ int g_candcnt;
__device__ int g_cnt2;
__device__ u64 g_cand[CAPBIG];
__device__ float4 g_boxstore[TOT];       // written sparsely; only written slots read
__device__ u64 g_sortbuf[SORTN];
__device__ float4 g_boxes[PRE];
__device__ float  g_area[PRE];
__device__ u64 g_supp[WPITCH];
__device__ u64 g_mask[(size_t)PRE * WPITCH];

// ---------------- software grid barrier (volatile-read poll) ----------------
__device__ __forceinline__ void gbar()
{
    __syncthreads();
    if (threadIdx.x == 0) {
        __threadfence();
        u32 nb = gridDim.x;
        u32 my = atomicAdd(&g_barcnt, 1u) + 1u;
        u32 rem = my % nb;
        u32 tgt = rem ? my + (nb - rem) : my;
        while ((int)(*(volatile u32*)&g_barcnt - tgt) < 0) { }
        __threadfence();
    }
    __syncthreads();
}

// ---------------- ordered score bits ----------------
__device__ __forceinline__ u32 obits(float score)
{
    u32 sb = __float_as_uint(score);
    return (sb & 0x80000000u) ? ~sb : (sb | 0x80000000u);
}

// ---------------- box decode (explicit RN: match XLA no-fma) ----------------
__device__ __forceinline__ float4 decode_box(int pix, int a,
                                             const float* __restrict__ del,
                                             const float4* __restrict__ anc,
                                             float imW1, float imH1, float ms,
                                             bool& valid)
{
    float sx = __fmul_rn((float)(pix & 255), 16.0f);
    float sy = __fmul_rn((float)(pix >> 8), 16.0f);
    float4 A = anc[a];
    float ax1 = __fadd_rn(A.x, sx);
    float ay1 = __fadd_rn(A.y, sy);
    float ax2 = __fadd_rn(A.z, sx);
    float ay2 = __fadd_rn(A.w, sy);
    float aw  = __fadd_rn(__fsub_rn(ax2, ax1), 1.0f);
    float ah  = __fadd_rn(__fsub_rn(ay2, ay1), 1.0f);
    float acx = __fadd_rn(ax1, __fmul_rn(0.5f, aw));
    float acy = __fadd_rn(ay1, __fmul_rn(0.5f, ah));

    int base = (4 * a) * HWPIX + pix;
    float dx = del[base];
    float dy = del[base + HWPIX];
    float dw = del[base + 2 * HWPIX];
    float dh = del[base + 3 * HWPIX];
    dw = fminf(fmaxf(dw, -10.0f), 10.0f);
    dh = fminf(fmaxf(dh, -10.0f), 10.0f);

    float pcx = __fadd_rn(__fmul_rn(dx, aw), acx);
    float pcy = __fadd_rn(__fmul_rn(dy, ah), acy);
    float pw  = __fmul_rn(expf(dw), aw);
    float ph  = __fmul_rn(expf(dh), ah);

    float hx = __fmul_rn(0.5f, pw);
    float hy = __fmul_rn(0.5f, ph);
    float x1 = fminf(fmaxf(__fsub_rn(pcx, hx), 0.0f), imW1);
    float y1 = fminf(fmaxf(__fsub_rn(pcy, hy), 0.0f), imH1);
    float x2 = fminf(fmaxf(__fsub_rn(__fadd_rn(pcx, hx), 1.0f), 0.0f), imW1);
    float y2 = fminf(fmaxf(__fsub_rn(__fadd_rn(pcy, hy), 1.0f), 0.0f), imH1);

    valid = (__fadd_rn(__fsub_rn(x2, x1), 1.0f) >= ms) &&
            (__fadd_rn(__fsub_rn(y2, y1), 1.0f) >= ms);
    return make_float4(x1, y1, x2, y2);
}

// ---------------- parallel threshold search (block 0, 1024 thr) ----------------
__device__ __forceinline__ void threshold_search(const u32* __restrict__ hist,
                                                 int target, int* outBin,
                                                 u32* outAbove, u32* outTotal)
{
    __shared__ u32 co[1024];
    __shared__ u32 fs[64];
    __shared__ int c_blk;
    __shared__ u32 above_c;
    int t = threadIdx.x;

    u32 s = 0;
#pragma unroll 8
    for (int b = 0; b < 64; ++b) s += hist[t * 64 + b];
    u32 cur = s;
    co[t] = cur;
    __syncthreads();
    for (int off = 1; off < 1024; off <<= 1) {
        u32 oth = (t + off < 1024) ? co[t + off] : 0u;
        __syncthreads();
        cur += oth;
        co[t] = cur;
        __syncthreads();
    }
    if (t == 0) { c_blk = -1; *outTotal = co[0]; }
    __syncthreads();
    u32 nxt = (t < 1023) ? co[t + 1] : 0u;
    if (cur >= (u32)target && nxt < (u32)target) { c_blk = t; above_c = nxt; }
    __syncthreads();

    int c = c_blk;
    if (c < 0) { if (t == 0) { *outBin = 0; *outAbove = 0u; } return; }
    if (t < 64) fs[t] = hist[c * 64 + t];
    __syncthreads();
    if (t == 0) {
        u32 acc = above_c;
        int b;
        for (b = 63; b >= 0; --b) {
            acc += fs[b];
            if (acc >= (u32)target) break;
        }
        if (b < 0) b = 0;
        *outBin = c * 64 + b;
        *outAbove = acc - fs[b];
    }
}

// ---------------- candidate scan pass (decode only above loose threshold) ----------------
// mode 0: push items with ob16 in [Tlo, inf)
// mode 1 (fallback): push items with ob16 in [0, Tlo)  (complement, avoids dupes)
__device__ __forceinline__ void scan_candidates(const float* __restrict__ fg,
                                                const float* __restrict__ del,
                                                const float4* __restrict__ anc,
                                                float imW1, float imH1, float ms,
                                                u32 Tlo, int mode,
                                                int gtid, int gs, int lane)
{
    for (int v4 = gtid; v4 < TOT / 4; v4 += gs) {
        int base = v4 * 4;
        float4 sc = *(const float4*)(fg + base);
        float s4[4] = { sc.x, sc.y, sc.z, sc.w };
#pragma unroll
        for (int k = 0; k < 4; ++k) {
            u32 ob = obits(s4[k]);
            u32 ob16 = ob >> 16;
            bool inband = mode ? (ob16 < Tlo) : (ob16 >= Tlo);
            bool keep = false;
            float4 bx;
            int item = base + k;
            if (inband) {
                int a   = item >> 16;
                int pix = item & 65535;
                bool valid;
                bx = decode_box(pix, a, del, anc, imW1, imH1, ms, valid);
                keep = valid;
            }
            u32 m = __ballot_sync(0xFFFFFFFFu, keep);
            if (keep) {
                int rank = __popc(m & ((1u << lane) - 1));
                int leader = __ffs(m) - 1;
                int bp = 0;
                if (lane == leader) bp = atomicAdd(&g_candcnt, __popc(m));
                bp = __shfl_sync(m, bp, leader);
                int a   = item >> 16;
                int pix = item & 65535;
                int ti  = pix * NA + a;                 // pixel-major rank index
                int pos = bp + rank;
                if (pos < CAPBIG) {
                    g_cand[pos] = ((u64)ob << 32) | (u64)(0xFFFFFFFFu - (u32)ti);
                    g_boxstore[ti] = bx;
                    atomicAdd(&g_histv[ob16], 1u);
                }
            }
        }
    }
}

// ---------------- THE fused persistent kernel ----------------
__global__ void __launch_bounds__(NTHR, 1)
fused_proposal(const float* __restrict__ probs,
               const float* __restrict__ del,
               const float* __restrict__ img,
               const float* __restrict__ anchors,
               float* __restrict__ out)
{
    extern __shared__ u64 sk[];                     // 64KB dynamic (sort)
    __shared__ float4 cb[64];
    __shared__ float  ca[64];
    __shared__ int   sh_bin;
    __shared__ u32   sh_above, sh_total;

    const int tid  = threadIdx.x;
    const int gtid = blockIdx.x * NTHR + tid;
    const int gs   = gridDim.x * NTHR;
    const int nb   = gridDim.x;
    const int lane = tid & 31;

    const float* fg = probs + NA * HWPIX;
    const float4* anc = (const float4*)anchors;
    float imH1 = __fsub_rn(img[0], 1.0f);
    float imW1 = __fsub_rn(img[1], 1.0f);
    float ms   = __fmul_rn(16.0f, img[2]);

    // ---- P0: zero scratch ----
    for (int i = gtid; i < NBINS; i += gs) { g_hist1[i] = 0u; g_histv[i] = 0u; g_hist2[i] = 0u; }
    for (int i = gtid; i < SORTN; i += gs) g_sortbuf[i] = 0ull;
    for (int i = gtid; i < WPITCH; i += gs) g_supp[i] = 0ull;
    if (gtid == 0) { g_candcnt = 0; g_cnt2 = 0; g_fb = 0; }
    gbar();

    // ---- P1a: histogram of raw score bits (no decode) ----
    for (int v4 = gtid; v4 < TOT / 4; v4 += gs) {
        float4 sc = *(const float4*)(fg + v4 * 4);
        atomicAdd(&g_hist1[obits(sc.x) >> 16], 1u);
        atomicAdd(&g_hist1[obits(sc.y) >> 16], 1u);
        atomicAdd(&g_hist1[obits(sc.z) >> 16], 1u);
        atomicAdd(&g_hist1[obits(sc.w) >> 16], 1u);
    }
    gbar();

    // ---- P2a: loose threshold at rank CAPB_LOOSE ----
    if (blockIdx.x == 0) {
        threshold_search(g_hist1, CAPB_LOOSE, &sh_bin, &sh_above, &sh_total);
        __syncthreads();
        if (tid == 0) g_Tloose = sh_bin;
    }
    gbar();

    // ---- P3a: decode + push candidates above loose threshold ----
    {
        u32 Tlo = (u32)g_Tloose;
        scan_candidates(fg, del, anc, imW1, imH1, ms, Tlo, 0, gtid, gs, lane);
    }
    gbar();

    // ---- P4a: exact 16-bit threshold among valid candidates ----
    if (blockIdx.x == 0) {
        threshold_search(g_histv, PRE, &sh_bin, &sh_above, &sh_total);
        __syncthreads();
        if (tid == 0) {
            g_T1 = sh_bin; g_above = sh_above;
            g_fb = (sh_total < (u32)PRE && (u32)g_Tloose > 0u) ? 1 : 0;
        }
    }
    gbar();

    // ---- fallback: too few valid above loose threshold (rare) ----
    if (g_fb) {
        u32 Tlo = (u32)g_Tloose;
        scan_candidates(fg, del, anc, imW1, imH1, ms, Tlo, 1, gtid, gs, lane);
        gbar();
        if (blockIdx.x == 0) {
            threshold_search(g_histv, PRE, &sh_bin, &sh_above, &sh_total);
            __syncthreads();
            if (tid == 0) { g_T1 = sh_bin; g_above = sh_above; }
        }
        gbar();
    }

    // ---- P4b: low-16-bit histogram for boundary bin ----
    {
        int cc = g_candcnt; if (cc > CAPBIG) cc = CAPBIG;
        u32 T1 = (u32)g_T1;
        for (int i = gtid; i < cc; i += gs) {
            u64 key = g_cand[i];
            if ((u32)(key >> 48) == T1)
                atomicAdd(&g_hist2[(u32)(key >> 32) & 0xFFFFu], 1u);
        }
    }
    gbar();

    // ---- P4c: low-bit threshold -> final 64-bit threshold ----
    if (blockIdx.x == 0) {
        int need = PRE - (int)g_above;
        threshold_search(g_hist2, need, &sh_bin, &sh_above, &sh_total);
        __syncthreads();
        if (tid == 0)
            g_thr64 = ((u64)(u32)g_T1 << 48) | ((u64)(u32)sh_bin << 32);
    }
    gbar();

    // ---- P5: filter into sort buffer ----
    {
        int cc = g_candcnt; if (cc > CAPBIG) cc = CAPBIG;
        u64 thr = g_thr64;
        for (int i = gtid; i < cc; i += gs) {
            u64 key = g_cand[i];
            if (key >= thr) {
                int pos = atomicAdd(&g_cnt2, 1);
                if (pos < SORTN) g_sortbuf[pos] = key;
            }
        }
    }
    gbar();

    // ---- P6: presort 4 chunks of 2048 (blocks 0-3) ----
    if (blockIdx.x < 4) {
        int base = blockIdx.x * 2048;
        for (int t = tid; t < 2048; t += NTHR) sk[t] = g_sortbuf[base + t];
        __syncthreads();
        for (int k = 2; k <= 2048; k <<= 1) {
            for (int j = k >> 1; j > 0; j >>= 1) {
                for (int t = tid; t < 2048; t += NTHR) {
                    int l = t ^ j;
                    if (l > t) {
                        u64 a = sk[t], b = sk[l];
                        bool sw = (((base + t) & k) == 0) ? (a < b) : (a > b);
                        if (sw) { sk[t] = b; sk[l] = a; }
                    }
                }
                __syncthreads();
            }
        }
        for (int t = tid; t < 2048; t += NTHR) g_sortbuf[base + t] = sk[t];
    }
    gbar();

    // ---- P7: k=4096 merge in smem (blocks 0-1) ----
    if (blockIdx.x < 2) {
        int base = blockIdx.x * 4096;
        for (int t = tid; t < 4096; t += NTHR) sk[t] = g_sortbuf[base + t];
        __syncthreads();
        for (int j = 2048; j > 0; j >>= 1) {
            for (int t = tid; t < 4096; t += NTHR) {
                int l = t ^ j;
                if (l > t) {
                    u64 a = sk[t], b = sk[l];
                    bool sw = (((base + t) & 4096) == 0) ? (a < b) : (a > b);
                    if (sw) { sk[t] = b; sk[l] = a; }
                }
            }
            __syncthreads();
        }
        for (int t = tid; t < 4096; t += NTHR) g_sortbuf[base + t] = sk[t];
    }
    gbar();

    // ---- P8: k=8192 final merge in smem (block 0) ----
    if (blockIdx.x == 0) {
        for (int t = tid; t < 8192; t += NTHR) sk[t] = g_sortbuf[t];
        __syncthreads();
        for (int j = 4096; j > 0; j >>= 1) {
            for (int t = tid; t < 8192; t += NTHR) {
                int l = t ^ j;
                if (l > t) {
                    u64 a = sk[t], b = sk[l];
                    if (a < b) { sk[t] = b; sk[l] = a; }
                }
            }
            __syncthreads();
        }
        for (int t = tid; t < 8192; t += NTHR) g_sortbuf[t] = sk[t];
    }
    gbar();

    // ---- P9: gather top-6000 boxes + areas ----
    for (int t = gtid; t < PRE; t += gs) {
        u64 key = g_sortbuf[t];
        float4 bx;
        if (key == 0ull) {
            atomicOr(&g_supp[t >> 6], 1ull << (t & 63));
            bx = make_float4(0.f, 0.f, 0.f, 0.f);
        } else {
            u32 ti = 0xFFFFFFFFu - (u32)(key & 0xFFFFFFFFull);
            bx = g_boxstore[ti];
        }
        g_boxes[t] = bx;
        g_area[t] = __fmul_rn(__fadd_rn(__fsub_rn(bx.z, bx.x), 1.0f),
                              __fadd_rn(__fsub_rn(bx.w, bx.y), 1.0f));
    }
    gbar();

    // ---- P10: IoU bitmask tiles ----
    for (int tile = blockIdx.x; tile < NWORDS * 6; tile += nb) {
        int cB = tile % NWORDS;
        int rb = tile / NWORDS;
        int j0 = cB * 64;
        __syncthreads();
        if (tid < 64) {
            int j = j0 + tid;
            if (j < PRE) { cb[tid] = g_boxes[j]; ca[tid] = g_area[j]; }
            else         { cb[tid] = make_float4(0.f, 0.f, -1.f, -1.f); ca[tid] = 0.f; }
        }
        __syncthreads();
        int i = rb * NTHR + tid;
        if (i < PRE) {
            u64 word = 0ull;
            int c0 = (i >= j0) ? (i - j0 + 1) : 0;
            int cmax = min(64, PRE - j0);
            if (c0 < cmax) {
                float4 bi = g_boxes[i];
                float ai = g_area[i];
                for (int c = c0; c < cmax; ++c) {
                    float4 bj = cb[c];
                    float ix1 = fmaxf(bi.x, bj.x);
                    float iy1 = fmaxf(bi.y, bj.y);
                    float ix2 = fminf(bi.z, bj.z);
                    float iy2 = fminf(bi.w, bj.w);
                    float iw = fmaxf(__fadd_rn(__fsub_rn(ix2, ix1), 1.0f), 0.0f);
                    float ih = fmaxf(__fadd_rn(__fsub_rn(iy2, iy1), 1.0f), 0.0f);
                    float inter = __fmul_rn(iw, ih);
                    float u = __fsub_rn(__fadd_rn(ai, ca[c]), inter);
                    float t7  = __fmul_rn(NMS_T, u);
                    float d   = __fsub_rn(inter, t7);
                    float mar = __fmul_rn(2e-6f, u);
                    bool sup;
                    if (fabsf(d) <= mar) sup = (__fdiv_rn(inter, u) > NMS_T);
                    else                 sup = (d > 0.0f);
                    if (sup) word |= (1ull << c);
                }
            }
            g_mask[(size_t)i * WPITCH + cB] = word;
        }
    }
    gbar();

    // ---- P11: sequential NMS scan (block 0, warp 0) ----
    if (blockIdx.x != 0) return;
    if (tid < 32) {
        u64 S0 = g_supp[lane];
        u64 S1 = g_supp[lane + 32];
        u64 S2 = (lane < 30) ? g_supp[lane + 64] : 0ull;

        // prefetch window 0 diag words
        u64 d_lo = g_mask[(size_t)lane * WPITCH + 0];
        u64 d_hi = g_mask[(size_t)(lane + 32) * WPITCH + 0];

        int kept = 0;
        for (int wi = 0; wi < NWORDS && kept < POST; ++wi) {
            u64 cur_lo = d_lo, cur_hi = d_hi;
            // prefetch next window's diagonal early (independent of S)
            int wn = wi + 1;
            if (wn < NWORDS) {
                int r_lo = wn * 64 + lane;
                int r_hi = r_lo + 32;
                d_lo = g_mask[(size_t)r_lo * WPITCH + wn];
                d_hi = (r_hi < PRE) ? g_mask[(size_t)r_hi * WPITCH + wn] : 0ull;
            }

            int slot = wi >> 5, src = wi & 31;
            u64 mine = (slot == 0) ? S0 : ((slot == 1) ? S1 : S2);
            u64 w = __shfl_sync(0xFFFFFFFFu, mine, src);
            u64 alive = ~w;
            int bmax = min(64, PRE - wi * 64);
            if (bmax < 64) alive &= (1ull << bmax) - 1ull;

            while (alive && kept < POST) {
                int b = __ffsll(alive) - 1;
                alive &= alive - 1ull;
                int i = wi * 64 + b;

                const float* bp = (const float*)&g_boxes[i];
                if (lane < 4)       out[kept * 5 + 1 + lane] = bp[lane];
                else if (lane == 4) out[kept * 5] = 0.0f;
                kept++;

                size_t base = (size_t)i * WPITCH;
                S0 |= g_mask[base + lane];
                S1 |= g_mask[base + lane + 32];
                if (lane < 30) S2 |= g_mask[base + lane + 64];

                u64 dwb = __shfl_sync(0xFFFFFFFFu, (b < 32) ? cur_lo : cur_hi, b & 31);
                alive &= ~dwb;
            }
        }
        int rem = (POST - kept) * 5;
        for (int z = lane; z < rem; z += 32)
            out[kept * 5 + z] = 0.0f;
    }
}

// ---------------- launch: ONE persistent kernel ----------------
extern "C" void kernel_launch(void* const* d_in, const int* in_sizes, int n_in,
                              void* d_out, int out_size)
{
    const float* probs   = (const float*)d_in[0];
    const float* del     = (const float*)d_in[1];
    const float* img     = (const float*)d_in[2];
    const float* anchors = (const float*)d_in[3];
    float* out = (float*)d_out;

    cudaFuncSetAttribute(fused_proposal,
                         cudaFuncAttributeMaxDynamicSharedMemorySize, 65536);
    int dev = 0;
    cudaGetDevice(&dev);
    int nsm = 0;
    cudaDeviceGetAttribute(&nsm, cudaDevAttrMultiProcessorCount, dev);
    if (nsm < 8) nsm = 8;

    fused_proposal<<<nsm, NTHR, 65536>>>(probs, del, img, anchors, out);
}

// round 8
// speedup vs baseline: 1.4801x; 1.4801x over previous
#include <cuda_runtime.h>
#include <cstdint>

typedef unsigned long long u64;
typedef unsigned int u32;

// ---------------- problem constants ----------------
#define NA 9
#define HWPIX 65536
#define TOT 589824
#define PRE 6000
#define POST 300
#define NMS_T 0.7f
#define NWORDS 94
#define WPITCH 96
#define CAPBIG 16384
#define LOOSE_TARGET 7000
#define SORTN 8192
#define NBINS 65536
#define UBINS 4096
#define NTHR 1024

// ---------------- scratch ----------------
__device__ u32 g_barcnt;                 // monotonic across replays
__device__ u32 g_histb[UBINS];           // uniform score-value bins
__device__ u32 g_histv[NBINS];           // ob16 histogram of VALID candidates
__device__ u32 g_hist2[NBINS];           // low-16 histogram at boundary bin
__device__ int g_Tloose;
__device__ int g_T1;
__device__ u32 g_above;
__device__ int g_fb;
__device__ u64 g_thr64;
__device__ int g_candcnt;
__device__ int g_cnt2;
__device__ u64 g_cand[CAPBIG];
__device__ float4 g_boxstore[TOT];       // sparse: only candidate slots written/read
__device__ u64 g_sortbuf[SORTN];
__device__ float4 g_boxes[PRE];
__device__ float  g_area[PRE];
__device__ u64 g_supp[WPITCH];
__device__ u64 g_mask[(size_t)PRE * WPITCH];

// ---------------- software grid barrier ----------------
__device__ __forceinline__ void gbar()
{
    __syncthreads();
    if (threadIdx.x == 0) {
        __threadfence();
        u32 nb = gridDim.x;
        u32 my = atomicAdd(&g_barcnt, 1u) + 1u;
        u32 rem = my % nb;
        u32 tgt = rem ? my + (nb - rem) : my;
        while ((int)(*(volatile u32*)&g_barcnt - tgt) < 0) { }
        __threadfence();
    }
    __syncthreads();
}

// ---------------- ordered score bits ----------------
__device__ __forceinline__ u32 obits(float score)
{
    u32 sb = __float_as_uint(score);
    return (sb & 0x80000000u) ? ~sb : (sb | 0x80000000u);
}

// uniform monotone bin of a score
__device__ __forceinline__ int ubin(float s)
{
    int b = (int)__fmul_rn(s, 4096.0f);
    return max(0, min(UBINS - 1, b));
}

// ---------------- box decode (explicit RN: match XLA no-fma) ----------------
__device__ __forceinline__ float4 decode_box(int pix, int a,
                                             const float* __restrict__ del,
                                             const float4* __restrict__ anc,
                                             float imW1, float imH1, float ms,
                                             bool& valid)
{
    float sx = __fmul_rn((float)(pix & 255), 16.0f);
    float sy = __fmul_rn((float)(pix >> 8), 16.0f);
    float4 A = anc[a];
    float ax1 = __fadd_rn(A.x, sx);
    float ay1 = __fadd_rn(A.y, sy);
    float ax2 = __fadd_rn(A.z, sx);
    float ay2 = __fadd_rn(A.w, sy);
    float aw  = __fadd_rn(__fsub_rn(ax2, ax1), 1.0f);
    float ah  = __fadd_rn(__fsub_rn(ay2, ay1), 1.0f);
    float acx = __fadd_rn(ax1, __fmul_rn(0.5f, aw));
    float acy = __fadd_rn(ay1, __fmul_rn(0.5f, ah));

    int base = (4 * a) * HWPIX + pix;
    float dx = del[base];
    float dy = del[base + HWPIX];
    float dw = del[base + 2 * HWPIX];
    float dh = del[base + 3 * HWPIX];
    dw = fminf(fmaxf(dw, -10.0f), 10.0f);
    dh = fminf(fmaxf(dh, -10.0f), 10.0f);

    float pcx = __fadd_rn(__fmul_rn(dx, aw), acx);
    float pcy = __fadd_rn(__fmul_rn(dy, ah), acy);
    float pw  = __fmul_rn(expf(dw), aw);
    float ph  = __fmul_rn(expf(dh), ah);

    float hx = __fmul_rn(0.5f, pw);
    float hy = __fmul_rn(0.5f, ph);
    float x1 = fminf(fmaxf(__fsub_rn(pcx, hx), 0.0f), imW1);
    float y1 = fminf(fmaxf(__fsub_rn(pcy, hy), 0.0f), imH1);
    float x2 = fminf(fmaxf(__fsub_rn(__fadd_rn(pcx, hx), 1.0f), 0.0f), imW1);
    float y2 = fminf(fmaxf(__fsub_rn(__fadd_rn(pcy, hy), 1.0f), 0.0f), imH1);

    valid = (__fadd_rn(__fsub_rn(x2, x1), 1.0f) >= ms) &&
            (__fadd_rn(__fsub_rn(y2, y1), 1.0f) >= ms);
    return make_float4(x1, y1, x2, y2);
}

// ---------------- loose threshold over 4096 uniform bins (block 0) ----------------
__device__ __forceinline__ void loose_search(int target)
{
    __shared__ u32 co[1024];
    __shared__ int cth;
    __shared__ u32 cnxt;
    int t = threadIdx.x;
    u32 l0 = g_histb[4 * t + 0], l1 = g_histb[4 * t + 1];
    u32 l2 = g_histb[4 * t + 2], l3 = g_histb[4 * t + 3];
    u32 cur = l0 + l1 + l2 + l3;
    co[t] = cur;
    __syncthreads();
    for (int off = 1; off < 1024; off <<= 1) {
        u32 o = (t + off < 1024) ? co[t + off] : 0u;
        __syncthreads();
        cur += o;
        co[t] = cur;
        __syncthreads();
    }
    if (t == 0) cth = -1;
    __syncthreads();
    u32 nxt = (t < 1023) ? co[t + 1] : 0u;
    if (cur >= (u32)target && nxt < (u32)target) { cth = t; cnxt = nxt; }
    __syncthreads();
    if (t == 0) {
        int bin; u32 acc;
        if (cth < 0) { bin = 0; acc = co[0]; }      // fewer than target total
        else {
            acc = cnxt; bin = cth * 4;
            for (int b = 3; b >= 0; --b) {
                u32 h = g_histb[cth * 4 + b];
                acc += h;
                if (acc >= (u32)target) { bin = cth * 4 + b; break; }
            }
        }
        // capacity guard: keep raw candidate count <= CAPBIG, >= PRE if possible
        while (acc > (u32)CAPBIG && bin < UBINS - 1) {
            u32 hb = g_histb[bin];
            if (acc - hb < (u32)PRE) break;
            acc -= hb; bin++;
        }
        g_Tloose = bin;
    }
}

// ---------------- exact threshold search over 65536 bins (block 0) ----------------
__device__ __forceinline__ void threshold_search(const u32* __restrict__ hist,
                                                 int target, int* outBin,
                                                 u32* outAbove, u32* outTotal)
{
    __shared__ u32 co[1024];
    __shared__ u32 fs[64];
    __shared__ int c_blk;
    __shared__ u32 above_c;
    int t = threadIdx.x;

    u32 s = 0;
#pragma unroll 8
    for (int b = 0; b < 64; ++b) s += hist[t * 64 + b];
    u32 cur = s;
    co[t] = cur;
    __syncthreads();
    for (int off = 1; off < 1024; off <<= 1) {
        u32 oth = (t + off < 1024) ? co[t + off] : 0u;
        __syncthreads();
        cur += oth;
        co[t] = cur;
        __syncthreads();
    }
    if (t == 0) { c_blk = -1; *outTotal = co[0]; }
    __syncthreads();
    u32 nxt = (t < 1023) ? co[t + 1] : 0u;
    if (cur >= (u32)target && nxt < (u32)target) { c_blk = t; above_c = nxt; }
    __syncthreads();

    int c = c_blk;
    if (c < 0) { if (t == 0) { *outBin = 0; *outAbove = 0u; } return; }
    if (t < 64) fs[t] = hist[c * 64 + t];
    __syncthreads();
    if (t == 0) {
        u32 acc = above_c;
        int b;
        for (b = 63; b >= 0; --b) {
            acc += fs[b];
            if (acc >= (u32)target) break;
        }
        if (b < 0) b = 0;
        *outBin = c * 64 + b;
        *outAbove = acc - fs[b];
    }
}

// ---------------- candidate scan: push valid items with binLo <= ubin < binHi ----------------
__device__ __forceinline__ void scan_candidates(const float* __restrict__ fg,
                                                const float* __restrict__ del,
                                                const float4* __restrict__ anc,
                                                float imW1, float imH1, float ms,
                                                int binLo, int binHi,
                                                int gtid, int gs, int lane)
{
    for (int v4 = gtid; v4 < TOT / 4; v4 += gs) {
        int base = v4 * 4;
        float4 sc = *(const float4*)(fg + base);
        float s4[4] = { sc.x, sc.y, sc.z, sc.w };
#pragma unroll
        for (int k = 0; k < 4; ++k) {
            int bn = ubin(s4[k]);
            bool inband = (bn >= binLo) && (bn < binHi);
            bool keep = false;
            float4 bx;
            int item = base + k;
            if (inband) {
                int a   = item >> 16;
                int pix = item & 65535;
                bool valid;
                bx = decode_box(pix, a, del, anc, imW1, imH1, ms, valid);
                keep = valid;
            }
            u32 m = __ballot_sync(0xFFFFFFFFu, keep);
            if (keep) {
                int rank = __popc(m & ((1u << lane) - 1));
                int leader = __ffs(m) - 1;
                int bp = 0;
                if (lane == leader) bp = atomicAdd(&g_candcnt, __popc(m));
                bp = __shfl_sync(m, bp, leader);
                int a   = item >> 16;
                int pix = item & 65535;
                int ti  = pix * NA + a;
                int pos = bp + rank;
                if (pos < CAPBIG) {
                    u32 ob = obits(s4[k]);
                    g_cand[pos] = ((u64)ob << 32) | (u64)(0xFFFFFFFFu - (u32)ti);
                    g_boxstore[ti] = bx;
                    atomicAdd(&g_histv[ob >> 16], 1u);
                }
            }
        }
    }
}

// ---------------- THE fused persistent kernel ----------------
__global__ void __launch_bounds__(NTHR, 1)
fused_proposal(const float* __restrict__ probs,
               const float* __restrict__ del,
               const float* __restrict__ img,
               const float* __restrict__ anchors,
               float* __restrict__ out)
{
    extern __shared__ u64 sk[];                     // 64KB dynamic
    __shared__ float4 cb[64];
    __shared__ float  ca[64];
    __shared__ int   sh_bin;
    __shared__ u32   sh_above, sh_total;

    const int tid  = threadIdx.x;
    const int gtid = blockIdx.x * NTHR + tid;
    const int gs   = gridDim.x * NTHR;
    const int nb   = gridDim.x;
    const int lane = tid & 31;

    const float* fg = probs + NA * HWPIX;
    const float4* anc = (const float4*)anchors;
    float imH1 = __fsub_rn(img[0], 1.0f);
    float imW1 = __fsub_rn(img[1], 1.0f);
    float ms   = __fmul_rn(16.0f, img[2]);

    // ---- P0: zero scratch ----
    for (int i = gtid; i < NBINS; i += gs) { g_histv[i] = 0u; g_hist2[i] = 0u; }
    for (int i = gtid; i < UBINS; i += gs) g_histb[i] = 0u;
    for (int i = gtid; i < SORTN; i += gs) g_sortbuf[i] = 0ull;
    for (int i = gtid; i < WPITCH; i += gs) g_supp[i] = 0ull;
    if (gtid == 0) { g_candcnt = 0; g_cnt2 = 0; g_fb = 0; }
    gbar();

    // ---- P1: uniform-bin histogram, smem-privatized (contention-free) ----
    {
        u32* shh = (u32*)sk;
        for (int i = tid; i < UBINS; i += NTHR) shh[i] = 0u;
        __syncthreads();
        for (int v4 = gtid; v4 < TOT / 4; v4 += gs) {
            float4 sc = *(const float4*)(fg + v4 * 4);
            atomicAdd(&shh[ubin(sc.x)], 1u);
            atomicAdd(&shh[ubin(sc.y)], 1u);
            atomicAdd(&shh[ubin(sc.z)], 1u);
            atomicAdd(&shh[ubin(sc.w)], 1u);
        }
        __syncthreads();
        for (int i = tid; i < UBINS; i += NTHR) {
            u32 c = shh[i];
            if (c) atomicAdd(&g_histb[i], c);
        }
    }
    gbar();

    // ---- P2: loose uniform-bin threshold at raw rank LOOSE_TARGET ----
    if (blockIdx.x == 0) loose_search(LOOSE_TARGET);
    gbar();

    // ---- P3: decode + push candidates (bin >= b*) ----
    scan_candidates(fg, del, anc, imW1, imH1, ms, g_Tloose, UBINS, gtid, gs, lane);
    gbar();

    // ---- P4a: exact ob16 threshold among valid candidates ----
    if (blockIdx.x == 0) {
        threshold_search(g_histv, PRE, &sh_bin, &sh_above, &sh_total);
        __syncthreads();
        if (tid == 0) {
            g_T1 = sh_bin; g_above = sh_above;
            g_fb = (sh_total < (u32)PRE && g_Tloose > 0) ? 1 : 0;
        }
    }
    gbar();

    // ---- fallback: extend band downward (never triggers on benign data) ----
    for (int it = 0; it < 4; ++it) {
        if (g_fb == 0) break;                       // uniform post-barrier read
        int oldb = g_Tloose;
        int newb = oldb - (64 << (2 * it));
        if (newb < 0) newb = 0;
        scan_candidates(fg, del, anc, imW1, imH1, ms, newb, oldb, gtid, gs, lane);
        if (gtid == 0) g_Tloose = newb;
        gbar();
        if (blockIdx.x == 0) {
            threshold_search(g_histv, PRE, &sh_bin, &sh_above, &sh_total);
            __syncthreads();
            if (tid == 0) {
                g_T1 = sh_bin; g_above = sh_above;
                g_fb = (sh_total < (u32)PRE && g_Tloose > 0) ? 1 : 0;
            }
        }
        gbar();
    }

    // ---- P4b: low-16-bit histogram for boundary bin (candidates only) ----
    {
        int cc = g_candcnt; if (cc > CAPBIG) cc = CAPBIG;
        u32 T1 = (u32)g_T1;
        for (int i = gtid; i < cc; i += gs) {
            u64 key = g_cand[i];
            if ((u32)(key >> 48) == T1)
                atomicAdd(&g_hist2[(u32)(key >> 32) & 0xFFFFu], 1u);
        }
    }
    gbar();

    // ---- P4c: final 64-bit threshold ----
    if (blockIdx.x == 0) {
        int need = PRE - (int)g_above;
        threshold_search(g_hist2, need, &sh_bin, &sh_above, &sh_total);
        __syncthreads();
        if (tid == 0)
            g_thr64 = ((u64)(u32)g_T1 << 48) | ((u64)(u32)sh_bin << 32);
    }
    gbar();

    // ---- P5: filter into sort buffer ----
    {
        int cc = g_candcnt; if (cc > CAPBIG) cc = CAPBIG;
        u64 thr = g_thr64;
        for (int i = gtid; i < cc; i += gs) {
            u64 key = g_cand[i];
            if (key >= thr) {
                int pos = atomicAdd(&g_cnt2, 1);
                if (pos < SORTN) g_sortbuf[pos] = key;
            }
        }
    }
    gbar();

    // ---- P6: presort 4 chunks of 2048 (blocks 0-3) ----
    if (blockIdx.x < 4) {
        int base = blockIdx.x * 2048;
        for (int t = tid; t < 2048; t += NTHR) sk[t] = g_sortbuf[base + t];
        __syncthreads();
        for (int k = 2; k <= 2048; k <<= 1) {
            for (int j = k >> 1; j > 0; j >>= 1) {
                for (int t = tid; t < 2048; t += NTHR) {
                    int l = t ^ j;
                    if (l > t) {
                        u64 a = sk[t], b = sk[l];
                        bool sw = (((base + t) & k) == 0) ? (a < b) : (a > b);
                        if (sw) { sk[t] = b; sk[l] = a; }
                    }
                }
                __syncthreads();
            }
        }
        for (int t = tid; t < 2048; t += NTHR) g_sortbuf[base + t] = sk[t];
    }
    gbar();

    // ---- P7: k=4096 merge in smem (blocks 0-1) ----
    if (blockIdx.x < 2) {
        int base = blockIdx.x * 4096;
        for (int t = tid; t < 4096; t += NTHR) sk[t] = g_sortbuf[base + t];
        __syncthreads();
        for (int j = 2048; j > 0; j >>= 1) {
            for (int t = tid; t < 4096; t += NTHR) {
                int l = t ^ j;
                if (l > t) {
                    u64 a = sk[t], b = sk[l];
                    bool sw = (((base + t) & 4096) == 0) ? (a < b) : (a > b);
                    if (sw) { sk[t] = b; sk[l] = a; }
                }
            }
            __syncthreads();
        }
        for (int t = tid; t < 4096; t += NTHR) g_sortbuf[base + t] = sk[t];
    }
    gbar();

    // ---- P8: k=8192 final merge in smem (block 0) ----
    if (blockIdx.x == 0) {
        for (int t = tid; t < 8192; t += NTHR) sk[t] = g_sortbuf[t];
        __syncthreads();
        for (int j = 4096; j > 0; j >>= 1) {
            for (int t = tid; t < 8192; t += NTHR) {
                int l = t ^ j;
                if (l > t) {
                    u64 a = sk[t], b = sk[l];
                    if (a < b) { sk[t] = b; sk[l] = a; }
                }
            }
            __syncthreads();
        }
        for (int t = tid; t < 8192; t += NTHR) g_sortbuf[t] = sk[t];
    }
    gbar();

    // ---- P9: gather top-6000 boxes + areas ----
    for (int t = gtid; t < PRE; t += gs) {
        u64 key = g_sortbuf[t];
        float4 bx;
        if (key == 0ull) {
            atomicOr(&g_supp[t >> 6], 1ull << (t & 63));
            bx = make_float4(0.f, 0.f, 0.f, 0.f);
        } else {
            u32 ti = 0xFFFFFFFFu - (u32)(key & 0xFFFFFFFFull);
            bx = g_boxstore[ti];
        }
        g_boxes[t] = bx;
        g_area[t] = __fmul_rn(__fadd_rn(__fsub_rn(bx.z, bx.x), 1.0f),
                              __fadd_rn(__fsub_rn(bx.w, bx.y), 1.0f));
    }
    gbar();

    // ---- P10: IoU bitmask tiles ----
    for (int tile = blockIdx.x; tile < NWORDS * 6; tile += nb) {
        int cB = tile % NWORDS;
        int rb = tile / NWORDS;
        int j0 = cB * 64;
        __syncthreads();
        if (tid < 64) {
            int j = j0 + tid;
            if (j < PRE) { cb[tid] = g_boxes[j]; ca[tid] = g_area[j]; }
            else         { cb[tid] = make_float4(0.f, 0.f, -1.f, -1.f); ca[tid] = 0.f; }
        }
        __syncthreads();
        int i = rb * NTHR + tid;
        if (i < PRE) {
            u64 word = 0ull;
            int c0 = (i >= j0) ? (i - j0 + 1) : 0;
            int cmax = min(64, PRE - j0);
            if (c0 < cmax) {
                float4 bi = g_boxes[i];
                float ai = g_area[i];
                for (int c = c0; c < cmax; ++c) {
                    float4 bj = cb[c];
                    float ix1 = fmaxf(bi.x, bj.x);
                    float iy1 = fmaxf(bi.y, bj.y);
                    float ix2 = fminf(bi.z, bj.z);
                    float iy2 = fminf(bi.w, bj.w);
                    float iw = fmaxf(__fadd_rn(__fsub_rn(ix2, ix1), 1.0f), 0.0f);
                    float ih = fmaxf(__fadd_rn(__fsub_rn(iy2, iy1), 1.0f), 0.0f);
                    float inter = __fmul_rn(iw, ih);
                    float u = __fsub_rn(__fadd_rn(ai, ca[c]), inter);
                    float t7  = __fmul_rn(NMS_T, u);
                    float d   = __fsub_rn(inter, t7);
                    float mar = __fmul_rn(2e-6f, u);
                    bool sup;
                    if (fabsf(d) <= mar) sup = (__fdiv_rn(inter, u) > NMS_T);
                    else                 sup = (d > 0.0f);
                    if (sup) word |= (1ull << c);
                }
            }
            g_mask[(size_t)i * WPITCH + cB] = word;
        }
    }
    gbar();

    // ---- P11: sequential NMS scan (block 0, warp 0) ----
    if (blockIdx.x != 0) return;
    if (tid < 32) {
        u64 S0 = g_supp[lane];
        u64 S1 = g_supp[lane + 32];
        u64 S2 = (lane < 30) ? g_supp[lane + 64] : 0ull;

        u64 d_lo = g_mask[(size_t)lane * WPITCH + 0];
        u64 d_hi = g_mask[(size_t)(lane + 32) * WPITCH + 0];

        int kept = 0;
        for (int wi = 0; wi < NWORDS && kept < POST; ++wi) {
            u64 cur_lo = d_lo, cur_hi = d_hi;
            int wn = wi + 1;
            if (wn < NWORDS) {
                int r_lo = wn * 64 + lane;
                int r_hi = r_lo + 32;
                d_lo = g_mask[(size_t)r_lo * WPITCH + wn];
                d_hi = (r_hi < PRE) ? g_mask[(size_t)r_hi * WPITCH + wn] : 0ull;
            }

            int slot = wi >> 5, src = wi & 31;
            u64 mine = (slot == 0) ? S0 : ((slot == 1) ? S1 : S2);
            u64 w = __shfl_sync(0xFFFFFFFFu, mine, src);
            u64 alive = ~w;
            int bmax = min(64, PRE - wi * 64);
            if (bmax < 64) alive &= (1ull << bmax) - 1ull;

            while (alive && kept < POST) {
                int b = __ffsll(alive) - 1;
                alive &= alive - 1ull;
                int i = wi * 64 + b;

                const float* bp = (const float*)&g_boxes[i];
                if (lane < 4)       out[kept * 5 + 1 + lane] = bp[lane];
                else if (lane == 4) out[kept * 5] = 0.0f;
                kept++;

                size_t base = (size_t)i * WPITCH;
                S0 |= g_mask[base + lane];
                S1 |= g_mask[base + lane + 32];
                if (lane < 30) S2 |= g_mask[base + lane + 64];

                u64 dwb = __shfl_sync(0xFFFFFFFFu, (b < 32) ? cur_lo : cur_hi, b & 31);
                alive &= ~dwb;
            }
        }
        int rem = (POST - kept) * 5;
        for (int z = lane; z < rem; z += 32)
            out[kept * 5 + z] = 0.0f;
    }
}

// ---------------- launch: ONE persistent kernel ----------------
extern "C" void kernel_launch(void* const* d_in, const int* in_sizes, int n_in,
                              void* d_out, int out_size)
{
    const float* probs   = (const float*)d_in[0];
    const float* del     = (const float*)d_in[1];
    const float* img     = (const float*)d_in[2];
    const float* anchors = (const float*)d_in[3];
    float* out = (float*)d_out;

    cudaFuncSetAttribute(fused_proposal,
                         cudaFuncAttributeMaxDynamicSharedMemorySize, 65536);
    int dev = 0;
    cudaGetDevice(&dev);
    int nsm = 0;
    cudaDeviceGetAttribute(&nsm, cudaDevAttrMultiProcessorCount, dev);
    if (nsm < 8) nsm = 8;

    fused_proposal<<<nsm, NTHR, 65536>>>(probs, del, img, anchors, out);
}

// round 9
// speedup vs baseline: 2.2214x; 1.5009x over previous
#include <cuda_runtime.h>
#include <cstdint>

typedef unsigned long long u64;
typedef unsigned int u32;

// ---------------- problem constants ----------------
#define NA 9
#define HWPIX 65536
#define TOT 589824
#define PRE 6000
#define POST 300
#define NMS_T 0.7f
#define NWORDS 94
#define WPITCH 96
#define CAPBIG 16384
#define CAPR 12288              // ranking capacity (keys cached in smem)
#define LOOSE_TARGET 6500
#define UBINS 4096
#define NTHR 1024
#define DSMEM (CAPR * 8)        // 96KB dynamic smem

// ---------------- scratch ----------------
__device__ u32 g_barcnt;                 // monotonic across replays
__device__ u32 g_histb[UBINS];           // uniform score bins (zeroed in P3 for next run)
__device__ int g_Tloose;
__device__ int g_candcnt;                // reset at end of P11
__device__ u64 g_cand[CAPBIG];
__device__ float4 g_boxstore[TOT];       // sparse
__device__ float4 g_boxes[PRE];
__device__ float  g_area[PRE];
__device__ u64 g_mask[(size_t)PRE * WPITCH];

// ---------------- software grid barrier ----------------
__device__ __forceinline__ void gbar()
{
    __syncthreads();
    if (threadIdx.x == 0) {
        __threadfence();
        u32 nb = gridDim.x;
        u32 my = atomicAdd(&g_barcnt, 1u) + 1u;
        u32 rem = my % nb;
        u32 tgt = rem ? my + (nb - rem) : my;
        while ((int)(*(volatile u32*)&g_barcnt - tgt) < 0) { }
        __threadfence();
    }
    __syncthreads();
}

__device__ __forceinline__ u32 obits(float score)
{
    u32 sb = __float_as_uint(score);
    return (sb & 0x80000000u) ? ~sb : (sb | 0x80000000u);
}

__device__ __forceinline__ int ubin(float s)
{
    int b = (int)__fmul_rn(s, 4096.0f);
    return max(0, min(UBINS - 1, b));
}

// ---------------- box decode (explicit RN: match XLA no-fma) ----------------
__device__ __forceinline__ float4 decode_box(int pix, int a,
                                             const float* __restrict__ del,
                                             const float4* __restrict__ anc,
                                             float imW1, float imH1, float ms,
                                             bool& valid)
{
    float sx = __fmul_rn((float)(pix & 255), 16.0f);
    float sy = __fmul_rn((float)(pix >> 8), 16.0f);
    float4 A = anc[a];
    float ax1 = __fadd_rn(A.x, sx);
    float ay1 = __fadd_rn(A.y, sy);
    float ax2 = __fadd_rn(A.z, sx);
    float ay2 = __fadd_rn(A.w, sy);
    float aw  = __fadd_rn(__fsub_rn(ax2, ax1), 1.0f);
    float ah  = __fadd_rn(__fsub_rn(ay2, ay1), 1.0f);
    float acx = __fadd_rn(ax1, __fmul_rn(0.5f, aw));
    float acy = __fadd_rn(ay1, __fmul_rn(0.5f, ah));

    int base = (4 * a) * HWPIX + pix;
    float dx = del[base];
    float dy = del[base + HWPIX];
    float dw = del[base + 2 * HWPIX];
    float dh = del[base + 3 * HWPIX];
    dw = fminf(fmaxf(dw, -10.0f), 10.0f);
    dh = fminf(fmaxf(dh, -10.0f), 10.0f);

    float pcx = __fadd_rn(__fmul_rn(dx, aw), acx);
    float pcy = __fadd_rn(__fmul_rn(dy, ah), acy);
    float pw  = __fmul_rn(expf(dw), aw);
    float ph  = __fmul_rn(expf(dh), ah);

    float hx = __fmul_rn(0.5f, pw);
    float hy = __fmul_rn(0.5f, ph);
    float x1 = fminf(fmaxf(__fsub_rn(pcx, hx), 0.0f), imW1);
    float y1 = fminf(fmaxf(__fsub_rn(pcy, hy), 0.0f), imH1);
    float x2 = fminf(fmaxf(__fsub_rn(__fadd_rn(pcx, hx), 1.0f), 0.0f), imW1);
    float y2 = fminf(fmaxf(__fsub_rn(__fadd_rn(pcy, hy), 1.0f), 0.0f), imH1);

    valid = (__fadd_rn(__fsub_rn(x2, x1), 1.0f) >= ms) &&
            (__fadd_rn(__fsub_rn(y2, y1), 1.0f) >= ms);
    return make_float4(x1, y1, x2, y2);
}

// ---------------- loose threshold over 4096 uniform bins (block 0) ----------------
__device__ __forceinline__ void loose_search(int target)
{
    __shared__ u32 co[1024];
    __shared__ int cth;
    __shared__ u32 cnxt;
    int t = threadIdx.x;
    u32 cur = g_histb[4 * t + 0] + g_histb[4 * t + 1]
            + g_histb[4 * t + 2] + g_histb[4 * t + 3];
    co[t] = cur;
    __syncthreads();
    for (int off = 1; off < 1024; off <<= 1) {
        u32 o = (t + off < 1024) ? co[t + off] : 0u;
        __syncthreads();
        cur += o;
        co[t] = cur;
        __syncthreads();
    }
    if (t == 0) cth = -1;
    __syncthreads();
    u32 nxt = (t < 1023) ? co[t + 1] : 0u;
    if (cur >= (u32)target && nxt < (u32)target) { cth = t; cnxt = nxt; }
    __syncthreads();
    if (t == 0) {
        int bin; u32 acc;
        if (cth < 0) { bin = 0; acc = co[0]; }
        else {
            acc = cnxt; bin = cth * 4;
            for (int b = 3; b >= 0; --b) {
                acc += g_histb[cth * 4 + b];
                if (acc >= (u32)target) { bin = cth * 4 + b; break; }
            }
        }
        // capacity guard: raw in-band count <= CAPR while staying >= PRE
        while (acc > (u32)CAPR && bin < UBINS - 1) {
            u32 hb = g_histb[bin];
            if (acc - hb < (u32)PRE) break;
            acc -= hb; bin++;
        }
        g_Tloose = bin;
    }
}

// ---------------- candidate scan: decode + push valid, binLo <= ubin < binHi ----------------
__device__ __forceinline__ void scan_candidates(const float* __restrict__ fg,
                                                const float* __restrict__ del,
                                                const float4* __restrict__ anc,
                                                float imW1, float imH1, float ms,
                                                int binLo, int binHi,
                                                int gtid, int gs, int lane)
{
    for (int v4 = gtid; v4 < TOT / 4; v4 += gs) {   // TOT/4 divisible by 32: warp-uniform
        int base = v4 * 4;
        float4 sc = *(const float4*)(fg + base);
        float s4[4] = { sc.x, sc.y, sc.z, sc.w };
#pragma unroll
        for (int k = 0; k < 4; ++k) {
            int bn = ubin(s4[k]);
            bool inband = (bn >= binLo) && (bn < binHi);
            bool keep = false;
            float4 bx;
            int item = base + k;
            if (inband) {
                int a   = item >> 16;
                int pix = item & 65535;
                bool valid;
                bx = decode_box(pix, a, del, anc, imW1, imH1, ms, valid);
                keep = valid;
            }
            u32 m = __ballot_sync(0xFFFFFFFFu, keep);
            if (keep) {
                int rank = __popc(m & ((1u << lane) - 1));
                int leader = __ffs(m) - 1;
                int bp = 0;
                if (lane == leader) bp = atomicAdd(&g_candcnt, __popc(m));
                bp = __shfl_sync(m, bp, leader);
                int a   = item >> 16;
                int pix = item & 65535;
                int ti  = pix * NA + a;
                int pos = bp + rank;
                if (pos < CAPBIG) {
                    u32 ob = obits(s4[k]);
                    g_cand[pos] = ((u64)ob << 32) | (u64)(0xFFFFFFFFu - (u32)ti);
                    g_boxstore[ti] = bx;
                }
            }
        }
    }
}

// ---------------- THE fused persistent kernel ----------------
__global__ void __launch_bounds__(NTHR, 1)
fused_proposal(const float* __restrict__ probs,
               const float* __restrict__ del,
               const float* __restrict__ img,
               const float* __restrict__ anchors,
               float* __restrict__ out)
{
    extern __shared__ u64 sk[];                     // 96KB dynamic
    __shared__ float4 cb[64];
    __shared__ float  ca[64];
    __shared__ u32    pr[32 * 32];

    const int tid  = threadIdx.x;
    const int gtid = blockIdx.x * NTHR + tid;
    const int gs   = gridDim.x * NTHR;
    const int nb   = gridDim.x;
    const int lane = tid & 31;
    const int wrp  = tid >> 5;

    const float* fg = probs + NA * HWPIX;
    const float4* anc = (const float4*)anchors;
    float imH1 = __fsub_rn(img[0], 1.0f);
    float imW1 = __fsub_rn(img[1], 1.0f);
    float ms   = __fmul_rn(16.0f, img[2]);

    // ---- P1: uniform-bin histogram, smem-privatized ----
    {
        u32* shh = (u32*)sk;
        for (int i = tid; i < UBINS; i += NTHR) shh[i] = 0u;
        __syncthreads();
        for (int v4 = gtid; v4 < TOT / 4; v4 += gs) {
            float4 sc = *(const float4*)(fg + v4 * 4);
            atomicAdd(&shh[ubin(sc.x)], 1u);
            atomicAdd(&shh[ubin(sc.y)], 1u);
            atomicAdd(&shh[ubin(sc.z)], 1u);
            atomicAdd(&shh[ubin(sc.w)], 1u);
        }
        __syncthreads();
        for (int i = tid; i < UBINS; i += NTHR) {
            u32 c = shh[i];
            if (c) atomicAdd(&g_histb[i], c);
        }
    }
    gbar();

    // ---- P2: loose threshold at raw rank LOOSE_TARGET ----
    if (blockIdx.x == 0) loose_search(LOOSE_TARGET);
    gbar();

    // ---- P3: decode + push candidates; also re-zero g_histb for next replay ----
    {
        int tl = g_Tloose;
        scan_candidates(fg, del, anc, imW1, imH1, ms, tl, UBINS, gtid, gs, lane);
        for (int i = gtid; i < UBINS; i += gs) g_histb[i] = 0u;
    }
    gbar();

    // ---- fallback: extend band downward if too few valid (never on benign data) ----
    for (int it = 0; it < 4; ++it) {
        int NCc = *(volatile int*)&g_candcnt;
        int tl  = *(volatile int*)&g_Tloose;
        if (NCc >= PRE || tl <= 0) break;
        int newb = tl - (64 << (2 * it));
        if (newb < 0) newb = 0;
        scan_candidates(fg, del, anc, imW1, imH1, ms, newb, tl, gtid, gs, lane);
        if (gtid == 0) g_Tloose = newb;
        gbar();
    }

    // ---- P4: rank-and-scatter (exact sort order, one barrier) ----
    {
        int NC = *(volatile int*)&g_candcnt;
        if (NC > CAPR) NC = CAPR;
        for (int i = tid; i < NC; i += NTHR) sk[i] = g_cand[i];
        __syncthreads();
        int NG = (NC + 31) >> 5;          // candidate groups of 32
        int CH = (NC + 31) >> 5;          // keys per warp (ceil NC/32)
        for (int g = blockIdx.x; g < NG; g += nb) {
            int ci = g * 32 + lane;
            u64 mykey = (ci < NC) ? sk[ci] : 0xFFFFFFFFFFFFFFFFull;
            int k0 = wrp * CH;
            int k1 = min(k0 + CH, NC);
            u32 cnt = 0;
            for (int k = k0; k < k1; ++k)
                cnt += (sk[k] > mykey) ? 1u : 0u;     // broadcast smem read
            pr[wrp * 32 + lane] = cnt;
            __syncthreads();
            if (wrp == 0) {
                u32 rank = 0;
#pragma unroll
                for (int ww = 0; ww < 32; ++ww) rank += pr[ww * 32 + lane];
                if (ci < NC && rank < PRE) {
                    u32 ti = 0xFFFFFFFFu - (u32)(mykey & 0xFFFFFFFFull);
                    float4 bx = g_boxstore[ti];
                    g_boxes[rank] = bx;
                    g_area[rank] = __fmul_rn(__fadd_rn(__fsub_rn(bx.z, bx.x), 1.0f),
                                             __fadd_rn(__fsub_rn(bx.w, bx.y), 1.0f));
                }
            }
            __syncthreads();
        }
    }
    gbar();

    // ---- P10: IoU bitmask tiles ----
    {
        int NC = *(volatile int*)&g_candcnt;
        int limit = min(NC, PRE);
        for (int tile = blockIdx.x; tile < NWORDS * 6; tile += nb) {
            int cB = tile % NWORDS;
            int rb = tile / NWORDS;
            int j0 = cB * 64;
            __syncthreads();
            if (tid < 64) {
                int j = j0 + tid;
                if (j < limit) { cb[tid] = g_boxes[j]; ca[tid] = g_area[j]; }
                else           { cb[tid] = make_float4(0.f, 0.f, -1.f, -1.f); ca[tid] = 0.f; }
            }
            __syncthreads();
            int i = rb * NTHR + tid;
            if (i < limit) {
                u64 word = 0ull;
                int c0 = (i >= j0) ? (i - j0 + 1) : 0;
                int cmax = min(64, limit - j0);
                if (c0 < cmax) {
                    float4 bi = g_boxes[i];
                    float ai = g_area[i];
                    for (int c = c0; c < cmax; ++c) {
                        float4 bj = cb[c];
                        float ix1 = fmaxf(bi.x, bj.x);
                        float iy1 = fmaxf(bi.y, bj.y);
                        float ix2 = fminf(bi.z, bj.z);
                        float iy2 = fminf(bi.w, bj.w);
                        float iw = fmaxf(__fadd_rn(__fsub_rn(ix2, ix1), 1.0f), 0.0f);
                        float ih = fmaxf(__fadd_rn(__fsub_rn(iy2, iy1), 1.0f), 0.0f);
                        float inter = __fmul_rn(iw, ih);
                        float u = __fsub_rn(__fadd_rn(ai, ca[c]), inter);
                        float t7  = __fmul_rn(NMS_T, u);
                        float d   = __fsub_rn(inter, t7);
                        float mar = __fmul_rn(2e-6f, u);
                        bool sup;
                        if (fabsf(d) <= mar) sup = (__fdiv_rn(inter, u) > NMS_T);
                        else                 sup = (d > 0.0f);
                        if (sup) word |= (1ull << c);
                    }
                }
                g_mask[(size_t)i * WPITCH + cB] = word;
            }
        }
    }
    gbar();

    // ---- P11: sequential NMS scan (block 0, warp 0) ----
    if (blockIdx.x != 0) return;
    if (tid < 32) {
        int NC = *(volatile int*)&g_candcnt;
        int limit = min(NC, PRE);
        u64 S0 = 0ull, S1 = 0ull, S2 = 0ull;

        u64 d_lo = (lane < limit) ? g_mask[(size_t)lane * WPITCH + 0] : 0ull;
        u64 d_hi = (lane + 32 < limit) ? g_mask[(size_t)(lane + 32) * WPITCH + 0] : 0ull;

        int kept = 0;
        for (int wi = 0; wi * 64 < limit && kept < POST; ++wi) {
            u64 cur_lo = d_lo, cur_hi = d_hi;
            int wn = wi + 1;
            if (wn * 64 < limit) {
                int r_lo = wn * 64 + lane;
                int r_hi = r_lo + 32;
                d_lo = (r_lo < limit) ? g_mask[(size_t)r_lo * WPITCH + wn] : 0ull;
                d_hi = (r_hi < limit) ? g_mask[(size_t)r_hi * WPITCH + wn] : 0ull;
            }

            int slot = wi >> 5, src = wi & 31;
            u64 mine = (slot == 0) ? S0 : ((slot == 1) ? S1 : S2);
            u64 w = __shfl_sync(0xFFFFFFFFu, mine, src);
            u64 alive = ~w;
            int bmax = min(64, limit - wi * 64);
            if (bmax < 64) alive &= (1ull << bmax) - 1ull;

            while (alive && kept < POST) {
                int b = __ffsll(alive) - 1;
                alive &= alive - 1ull;
                int i = wi * 64 + b;

                const float* bp = (const float*)&g_boxes[i];
                if (lane < 4)       out[kept * 5 + 1 + lane] = bp[lane];
                else if (lane == 4) out[kept * 5] = 0.0f;
                kept++;

                size_t base = (size_t)i * WPITCH;
                S0 |= g_mask[base + lane];
                S1 |= g_mask[base + lane + 32];
                if (lane < 30) S2 |= g_mask[base + lane + 64];

                u64 dwb = __shfl_sync(0xFFFFFFFFu, (b < 32) ? cur_lo : cur_hi, b & 31);
                alive &= ~dwb;
            }
        }
        int rem = (POST - kept) * 5;
        for (int z = lane; z < rem; z += 32)
            out[kept * 5 + z] = 0.0f;

        if (lane == 0) g_candcnt = 0;   // reset for next replay
    }
}

// ---------------- launch ----------------
extern "C" void kernel_launch(void* const* d_in, const int* in_sizes, int n_in,
                              void* d_out, int out_size)
{
    const float* probs   = (const float*)d_in[0];
    const float* del     = (const float*)d_in[1];
    const float* img     = (const float*)d_in[2];
    const float* anchors = (const float*)d_in[3];
    float* out = (float*)d_out;

    cudaFuncSetAttribute(fused_proposal,
                         cudaFuncAttributeMaxDynamicSharedMemorySize, DSMEM);
    int dev = 0;
    cudaGetDevice(&dev);
    int nsm = 0;
    cudaDeviceGetAttribute(&nsm, cudaDevAttrMultiProcessorCount, dev);
    if (nsm < 8) nsm = 8;

    fused_proposal<<<nsm, NTHR, DSMEM>>>(probs, del, img, anchors, out);
}

// round 11
// speedup vs baseline: 2.3612x; 1.0629x over previous
#include <cuda_runtime.h>
#include <cstdint>

typedef unsigned long long u64;
typedef unsigned int u32;

// ---------------- problem constants ----------------
#define NA 9
#define HWPIX 65536
#define TOT 589824
#define PRE 6000
#define POST 300
#define NMS_T 0.7f
#define NWORDS 94
#define WPITCH 96
#define CAPBIG 16384
#define CAPR 12288
#define LOOSE_TARGET 6500
#define UBINS 4096
#define NTHR 1024
#define DSMEM (CAPR * 8)
#define LAZY_WIN 32             // fast-scan window bound
#define LAZY_ROWS 2048          // rows covered by lazy tiles (= LAZY_WIN*64)
#define NTILES (NWORDS * 6)     // all tiles (94 cols x 6 row-blocks of 1024)
#define LTILES (LAZY_WIN * 2)   // lazy tiles (32 cols x 2 row-blocks)

// ---------------- scratch ----------------
__device__ u32 g_barcnt;                 // monotonic across replays
__device__ u32 g_histb[UBINS];
__device__ int g_Tloose;
__device__ int g_candcnt;
__device__ int g_ctrl;                   // 0=pending 1=done 2=need full tiles
__device__ u64 g_cand[CAPBIG];
__device__ float4 g_boxstore[TOT];
__device__ float4 g_boxes[PRE];
__device__ float  g_area[PRE];
__device__ u64 g_mask[(size_t)PRE * WPITCH];

// ---------------- software grid barrier ----------------
__device__ __forceinline__ void gbar()
{
    __syncthreads();
    if (threadIdx.x == 0) {
        __threadfence();
        u32 nb = gridDim.x;
        u32 my = atomicAdd(&g_barcnt, 1u) + 1u;
        u32 rem = my % nb;
        u32 tgt = rem ? my + (nb - rem) : my;
        while ((int)(*(volatile u32*)&g_barcnt - tgt) < 0) { }
        __threadfence();
    }
    __syncthreads();
}

__device__ __forceinline__ u32 obits(float score)
{
    u32 sb = __float_as_uint(score);
    return (sb & 0x80000000u) ? ~sb : (sb | 0x80000000u);
}

__device__ __forceinline__ int ubin(float s)
{
    int b = (int)__fmul_rn(s, 4096.0f);
    return max(0, min(UBINS - 1, b));
}

// ---------------- box decode (explicit RN: match XLA no-fma) ----------------
__device__ __forceinline__ float4 decode_box(int pix, int a,
                                             const float* __restrict__ del,
                                             const float4* __restrict__ anc,
                                             float imW1, float imH1, float ms,
                                             bool& valid)
{
    float sx = __fmul_rn((float)(pix & 255), 16.0f);
    float sy = __fmul_rn((float)(pix >> 8), 16.0f);
    float4 A = anc[a];
    float ax1 = __fadd_rn(A.x, sx);
    float ay1 = __fadd_rn(A.y, sy);
    float ax2 = __fadd_rn(A.z, sx);
    float ay2 = __fadd_rn(A.w, sy);
    float aw  = __fadd_rn(__fsub_rn(ax2, ax1), 1.0f);
    float ah  = __fadd_rn(__fsub_rn(ay2, ay1), 1.0f);
    float acx = __fadd_rn(ax1, __fmul_rn(0.5f, aw));
    float acy = __fadd_rn(ay1, __fmul_rn(0.5f, ah));

    int base = (4 * a) * HWPIX + pix;
    float dx = del[base];
    float dy = del[base + HWPIX];
    float dw = del[base + 2 * HWPIX];
    float dh = del[base + 3 * HWPIX];
    dw = fminf(fmaxf(dw, -10.0f), 10.0f);
    dh = fminf(fmaxf(dh, -10.0f), 10.0f);

    float pcx = __fadd_rn(__fmul_rn(dx, aw), acx);
    float pcy = __fadd_rn(__fmul_rn(dy, ah), acy);
    float pw  = __fmul_rn(expf(dw), aw);
    float ph  = __fmul_rn(expf(dh), ah);

    float hx = __fmul_rn(0.5f, pw);
    float hy = __fmul_rn(0.5f, ph);
    float x1 = fminf(fmaxf(__fsub_rn(pcx, hx), 0.0f), imW1);
    float y1 = fminf(fmaxf(__fsub_rn(pcy, hy), 0.0f), imH1);
    float x2 = fminf(fmaxf(__fsub_rn(__fadd_rn(pcx, hx), 1.0f), 0.0f), imW1);
    float y2 = fminf(fmaxf(__fsub_rn(__fadd_rn(pcy, hy), 1.0f), 0.0f), imH1);

    valid = (__fadd_rn(__fsub_rn(x2, x1), 1.0f) >= ms) &&
            (__fadd_rn(__fsub_rn(y2, y1), 1.0f) >= ms);
    return make_float4(x1, y1, x2, y2);
}

// ---------------- loose threshold over uniform bins (block 0) ----------------
__device__ __forceinline__ void loose_search(int target)
{
    __shared__ u32 co[1024];
    __shared__ int cth;
    __shared__ u32 cnxt;
    int t = threadIdx.x;
    u32 cur = g_histb[4 * t + 0] + g_histb[4 * t + 1]
            + g_histb[4 * t + 2] + g_histb[4 * t + 3];
    co[t] = cur;
    __syncthreads();
    for (int off = 1; off < 1024; off <<= 1) {
        u32 o = (t + off < 1024) ? co[t + off] : 0u;
        __syncthreads();
        cur += o;
        co[t] = cur;
        __syncthreads();
    }
    if (t == 0) cth = -1;
    __syncthreads();
    u32 nxt = (t < 1023) ? co[t + 1] : 0u;
    if (cur >= (u32)target && nxt < (u32)target) { cth = t; cnxt = nxt; }
    __syncthreads();
    if (t == 0) {
        int bin; u32 acc;
        if (cth < 0) { bin = 0; acc = co[0]; }
        else {
            acc = cnxt; bin = cth * 4;
            for (int b = 3; b >= 0; --b) {
                acc += g_histb[cth * 4 + b];
                if (acc >= (u32)target) { bin = cth * 4 + b; break; }
            }
        }
        while (acc > (u32)CAPR && bin < UBINS - 1) {
            u32 hb = g_histb[bin];
            if (acc - hb < (u32)PRE) break;
            acc -= hb; bin++;
        }
        g_Tloose = bin;
    }
}

// ---------------- candidate scan ----------------
__device__ __forceinline__ void scan_candidates(const float* __restrict__ fg,
                                                const float* __restrict__ del,
                                                const float4* __restrict__ anc,
                                                float imW1, float imH1, float ms,
                                                int binLo, int binHi,
                                                int gtid, int gs, int lane)
{
    for (int v4 = gtid; v4 < TOT / 4; v4 += gs) {
        int base = v4 * 4;
        float4 sc = *(const float4*)(fg + base);
        float s4[4] = { sc.x, sc.y, sc.z, sc.w };
#pragma unroll
        for (int k = 0; k < 4; ++k) {
            int bn = ubin(s4[k]);
            bool inband = (bn >= binLo) && (bn < binHi);
            bool keep = false;
            float4 bx;
            int item = base + k;
            if (inband) {
                int a   = item >> 16;
                int pix = item & 65535;
                bool valid;
                bx = decode_box(pix, a, del, anc, imW1, imH1, ms, valid);
                keep = valid;
            }
            u32 m = __ballot_sync(0xFFFFFFFFu, keep);
            if (keep) {
                int rank = __popc(m & ((1u << lane) - 1));
                int leader = __ffs(m) - 1;
                int bp = 0;
                if (lane == leader) bp = atomicAdd(&g_candcnt, __popc(m));
                bp = __shfl_sync(m, bp, leader);
                int a   = item >> 16;
                int pix = item & 65535;
                int ti  = pix * NA + a;
                int pos = bp + rank;
                if (pos < CAPBIG) {
                    u32 ob = obits(s4[k]);
                    g_cand[pos] = ((u64)ob << 32) | (u64)(0xFFFFFFFFu - (u32)ti);
                    g_boxstore[ti] = bx;
                }
            }
        }
    }
}

// ---------------- one IoU mask tile: 64 cols (cB), 1024 rows (rb) ----------------
__device__ __forceinline__ void iou_tile(int cB, int rb, int limit,
                                         float4* cb, float* ca, int tid)
{
    int j0 = cB * 64;
    __syncthreads();
    if (tid < 64) {
        int j = j0 + tid;
        if (j < limit) { cb[tid] = g_boxes[j]; ca[tid] = g_area[j]; }
        else           { cb[tid] = make_float4(0.f, 0.f, -1.f, -1.f); ca[tid] = 0.f; }
    }
    __syncthreads();
    int i = rb * NTHR + tid;
    if (i < limit) {
        u64 word = 0ull;
        int c0 = (i >= j0) ? (i - j0 + 1) : 0;
        int cmax = min(64, limit - j0);
        if (c0 < cmax) {
            float4 bi = g_boxes[i];
            float ai = g_area[i];
            for (int c = c0; c < cmax; ++c) {
                float4 bj = cb[c];
                float ix1 = fmaxf(bi.x, bj.x);
                float iy1 = fmaxf(bi.y, bj.y);
                float ix2 = fminf(bi.z, bj.z);
                float iy2 = fminf(bi.w, bj.w);
                float iw = fmaxf(__fadd_rn(__fsub_rn(ix2, ix1), 1.0f), 0.0f);
                float ih = fmaxf(__fadd_rn(__fsub_rn(iy2, iy1), 1.0f), 0.0f);
                float inter = __fmul_rn(iw, ih);
                float u = __fsub_rn(__fadd_rn(ai, ca[c]), inter);
                float t7  = __fmul_rn(NMS_T, u);
                float d   = __fsub_rn(inter, t7);
                float mar = __fmul_rn(2e-6f, u);
                bool sup;
                if (fabsf(d) <= mar) sup = (__fdiv_rn(inter, u) > NMS_T);
                else                 sup = (d > 0.0f);
                if (sup) word |= (1ull << c);
            }
        }
        g_mask[(size_t)i * WPITCH + cB] = word;
    }
}

// ---------------- sequential NMS scan (warp 0 of block 0) ----------------
// full=false: only S0 maintained (valid while winMax<=32)
__device__ __forceinline__ int nms_scan(float* __restrict__ out, int limit,
                                        int winMax, bool full, int lane)
{
    u64 S0 = 0ull, S1 = 0ull, S2 = 0ull;
    int nwin = min(winMax, (limit + 63) >> 6);

    u64 d_lo = (lane < limit) ? g_mask[(size_t)lane * WPITCH + 0] : 0ull;
    u64 d_hi = (lane + 32 < limit) ? g_mask[(size_t)(lane + 32) * WPITCH + 0] : 0ull;

    int kept = 0;
    for (int wi = 0; wi < nwin && kept < POST; ++wi) {
        u64 cur_lo = d_lo, cur_hi = d_hi;
        int wn = wi + 1;
        if (wn < nwin) {
            int r_lo = wn * 64 + lane;
            int r_hi = r_lo + 32;
            d_lo = (r_lo < limit) ? g_mask[(size_t)r_lo * WPITCH + wn] : 0ull;
            d_hi = (r_hi < limit) ? g_mask[(size_t)r_hi * WPITCH + wn] : 0ull;
        }

        int slot = wi >> 5, src = wi & 31;
        u64 mine = (slot == 0) ? S0 : ((slot == 1) ? S1 : S2);
        u64 w = __shfl_sync(0xFFFFFFFFu, mine, src);
        u64 alive = ~w;
        int bmax = min(64, limit - wi * 64);
        if (bmax < 64) alive &= (1ull << bmax) - 1ull;

        while (alive && kept < POST) {
            int b = __ffsll(alive) - 1;
            alive &= alive - 1ull;
            int i = wi * 64 + b;

            const float* bp = (const float*)&g_boxes[i];
            if (lane < 4)       out[kept * 5 + 1 + lane] = bp[lane];
            else if (lane == 4) out[kept * 5] = 0.0f;
            kept++;

            size_t base = (size_t)i * WPITCH;
            S0 |= g_mask[base + lane];
            if (full) {
                S1 |= g_mask[base + lane + 32];
                if (lane < 30) S2 |= g_mask[base + lane + 64];
            }

            u64 dwb = __shfl_sync(0xFFFFFFFFu, (b < 32) ? cur_lo : cur_hi, b & 31);
            alive &= ~dwb;
        }
    }
    return kept;
}

// ---------------- THE fused persistent kernel ----------------
__global__ void __launch_bounds__(NTHR, 1)
fused_proposal(const float* __restrict__ probs,
               const float* __restrict__ del,
               const float* __restrict__ img,
               const float* __restrict__ anchors,
               float* __restrict__ out)
{
    extern __shared__ u64 sk[];
    __shared__ float4 cb[64];
    __shared__ float  ca[64];
    __shared__ u32    pr[32 * 32];
    __shared__ int    sh_kept;
    __shared__ int    sh_ctrl;

    const int tid  = threadIdx.x;
    const int gtid = blockIdx.x * NTHR + tid;
    const int gs   = gridDim.x * NTHR;
    const int nb   = gridDim.x;
    const int lane = tid & 31;
    const int wrp  = tid >> 5;

    const float* fg = probs + NA * HWPIX;
    const float4* anc = (const float4*)anchors;
    float imH1 = __fsub_rn(img[0], 1.0f);
    float imW1 = __fsub_rn(img[1], 1.0f);
    float ms   = __fmul_rn(16.0f, img[2]);

    if (gtid == 0) *(volatile int*)&g_ctrl = 0;     // reset (ordered by first gbar)

    // ---- P1: uniform-bin histogram, smem-privatized ----
    {
        u32* shh = (u32*)sk;
        for (int i = tid; i < UBINS; i += NTHR) shh[i] = 0u;
        __syncthreads();
        for (int v4 = gtid; v4 < TOT / 4; v4 += gs) {
            float4 sc = *(const float4*)(fg + v4 * 4);
            atomicAdd(&shh[ubin(sc.x)], 1u);
            atomicAdd(&shh[ubin(sc.y)], 1u);
            atomicAdd(&shh[ubin(sc.z)], 1u);
            atomicAdd(&shh[ubin(sc.w)], 1u);
        }
        __syncthreads();
        for (int i = tid; i < UBINS; i += NTHR) {
            u32 c = shh[i];
            if (c) atomicAdd(&g_histb[i], c);
        }
    }
    gbar();

    // ---- P2: loose threshold ----
    if (blockIdx.x == 0) loose_search(LOOSE_TARGET);
    gbar();

    // ---- P3: decode + push candidates; re-zero g_histb for next replay ----
    {
        int tl = g_Tloose;
        scan_candidates(fg, del, anc, imW1, imH1, ms, tl, UBINS, gtid, gs, lane);
        for (int i = gtid; i < UBINS; i += gs) g_histb[i] = 0u;
    }
    gbar();

    // ---- fallback: extend band downward if too few valid ----
    for (int it = 0; it < 4; ++it) {
        int NCc = *(volatile int*)&g_candcnt;
        int tl  = *(volatile int*)&g_Tloose;
        if (NCc >= PRE || tl <= 0) break;
        int newb = tl - (64 << (2 * it));
        if (newb < 0) newb = 0;
        scan_candidates(fg, del, anc, imW1, imH1, ms, newb, tl, gtid, gs, lane);
        if (gtid == 0) g_Tloose = newb;
        gbar();
    }

    // ---- P4: rank-and-scatter ----
    {
        int NC = *(volatile int*)&g_candcnt;
        if (NC > CAPR) NC = CAPR;
        for (int i = tid; i < NC; i += NTHR) sk[i] = g_cand[i];
        __syncthreads();
        int NG = (NC + 31) >> 5;
        int CH = (NC + 31) >> 5;
        for (int g = blockIdx.x; g < NG; g += nb) {
            int ci = g * 32 + lane;
            u64 mykey = (ci < NC) ? sk[ci] : 0xFFFFFFFFFFFFFFFFull;
            int k0 = wrp * CH;
            int k1 = min(k0 + CH, NC);
            u32 cnt = 0;
            for (int k = k0; k < k1; ++k)
                cnt += (sk[k] > mykey) ? 1u : 0u;
            pr[wrp * 32 + lane] = cnt;
            __syncthreads();
            if (wrp == 0) {
                u32 rank = 0;
#pragma unroll
                for (int ww = 0; ww < 32; ++ww) rank += pr[ww * 32 + lane];
                if (ci < NC && rank < PRE) {
                    u32 ti = 0xFFFFFFFFu - (u32)(mykey & 0xFFFFFFFFull);
                    float4 bx = g_boxstore[ti];
                    g_boxes[rank] = bx;
                    g_area[rank] = __fmul_rn(__fadd_rn(__fsub_rn(bx.z, bx.x), 1.0f),
                                             __fadd_rn(__fsub_rn(bx.w, bx.y), 1.0f));
                }
            }
            __syncthreads();
        }
    }
    gbar();

    int NC = *(volatile int*)&g_candcnt;
    int limit = min(NC, PRE);

    // ---- P10a: LAZY IoU tiles (cols < 32, rows < 2048) ----
    for (int tile = blockIdx.x; tile < LTILES; tile += nb) {
        int cB = tile & (LAZY_WIN - 1);
        int rb = tile >> 5;
        iou_tile(cB, rb, limit, cb, ca, tid);
    }
    gbar();

    // ---- P11: bounded scan on block 0; others poll control word ----
    if (blockIdx.x == 0) {
        if (tid < 32) {
            int kept = nms_scan(out, limit, LAZY_WIN, false, lane);
            if (lane == 0) sh_kept = kept;
        }
        __syncthreads();
        bool ok = (sh_kept >= POST) || (limit <= LAZY_ROWS);
        if (tid == 0) {
            __threadfence();
            *(volatile int*)&g_ctrl = ok ? 1 : 2;
        }
        __syncthreads();
        if (ok) {
            // zero-fill remainder with all threads, reset counter, done
            int kept = sh_kept;
            int rem = (POST - kept) * 5;
            for (int z = tid; z < rem; z += NTHR)
                out[kept * 5 + z] = 0.0f;
            if (tid == 0) g_candcnt = 0;
            return;
        }
    } else {
        if (tid == 0) {
            int c;
            while ((c = *(volatile int*)&g_ctrl) == 0) { }
            sh_ctrl = c;
        }
        __syncthreads();
        if (sh_ctrl == 1) return;
    }

    // ---- rare path: compute remaining tiles, full rescan ----
    for (int tile = blockIdx.x; tile < NTILES; tile += nb) {
        int cB = tile % NWORDS;
        int rb = tile / NWORDS;
        if (cB < LAZY_WIN && rb < 2) continue;      // already done
        iou_tile(cB, rb, limit, cb, ca, tid);
    }
    gbar();

    if (blockIdx.x != 0) return;
    if (tid < 32) {
        int kept = nms_scan(out, limit, NWORDS, true, lane);
        int rem = (POST - kept) * 5;
        for (int z = lane; z < rem; z += 32)
            out[kept * 5 + z] = 0.0f;
        if (lane == 0) g_candcnt = 0;
    }
}

// ---------------- launch ----------------
extern "C" void kernel_launch(void* const* d_in, const int* in_sizes, int n_in,
                              void* d_out, int out_size)
{
    const float* probs   = (const float*)d_in[0];
    const float* del     = (const float*)d_in[1];
    const float* img     = (const float*)d_in[2];
    const float* anchors = (const float*)d_in[3];
    float* out = (float*)d_out;

    cudaFuncSetAttribute(fused_proposal,
                         cudaFuncAttributeMaxDynamicSharedMemorySize, DSMEM);
    int dev = 0;
    cudaGetDevice(&dev);
    int nsm = 0;
    cudaDeviceGetAttribute(&nsm, cudaDevAttrMultiProcessorCount, dev);
    if (nsm < 8) nsm = 8;

    fused_proposal<<<nsm, NTHR, DSMEM>>>(probs, del, img, anchors, out);
}

// round 13
// speedup vs baseline: 2.4763x; 1.0488x over previous
#include <cuda_runtime.h>
#include <cstdint>

typedef unsigned long long u64;
typedef unsigned int u32;

// ---------------- problem constants ----------------
#define NA 9
#define HWPIX 65536
#define TOT 589824
#define PRE 6000
#define POST 300
#define NMS_T 0.7f
#define NWORDS 94
#define WPITCH 96
#define CAPBIG 16384
#define CAPR 12288
#define LOOSE_TARGET 6500
#define UBINS 4096
#define T0BIN 4047              // speculative band: expect ~7050 items if scores ~U[0,1)
#define NTHR 1024
#define DSMEM (CAPR * 8)
#define LAZY_WIN 32
#define LAZY_ROWS 2048
#define NTILES (NWORDS * 6)
#define LTILES (LAZY_WIN * 2)

// ---------------- scratch ----------------
__device__ u32 g_barcnt;                 // monotonic across replays
__device__ u32 g_histb[UBINS];           // zero at entry; repair path re-zeroes after use
__device__ int g_Tloose;
__device__ int g_candcnt;
__device__ int g_ctrl;
__device__ u64 g_cand[CAPBIG];
__device__ float4 g_boxstore[TOT];
__device__ float4 g_boxes[PRE];
__device__ float  g_area[PRE];
__device__ u64 g_mask[(size_t)PRE * WPITCH];

// ---------------- software grid barrier ----------------
__device__ __forceinline__ void gbar()
{
    __syncthreads();
    if (threadIdx.x == 0) {
        __threadfence();
        u32 nb = gridDim.x;
        u32 my = atomicAdd(&g_barcnt, 1u) + 1u;
        u32 rem = my % nb;
        u32 tgt = rem ? my + (nb - rem) : my;
        while ((int)(*(volatile u32*)&g_barcnt - tgt) < 0) { }
        __threadfence();
    }
    __syncthreads();
}

__device__ __forceinline__ u32 obits(float score)
{
    u32 sb = __float_as_uint(score);
    return (sb & 0x80000000u) ? ~sb : (sb | 0x80000000u);
}

__device__ __forceinline__ int ubin(float s)
{
    int b = (int)__fmul_rn(s, 4096.0f);
    return max(0, min(UBINS - 1, b));
}

// ---------------- box decode (explicit RN: match XLA no-fma) ----------------
__device__ __forceinline__ float4 decode_box(int pix, int a,
                                             const float* __restrict__ del,
                                             const float4* __restrict__ anc,
                                             float imW1, float imH1, float ms,
                                             bool& valid)
{
    float sx = __fmul_rn((float)(pix & 255), 16.0f);
    float sy = __fmul_rn((float)(pix >> 8), 16.0f);
    float4 A = anc[a];
    float ax1 = __fadd_rn(A.x, sx);
    float ay1 = __fadd_rn(A.y, sy);
    float ax2 = __fadd_rn(A.z, sx);
    float ay2 = __fadd_rn(A.w, sy);
    float aw  = __fadd_rn(__fsub_rn(ax2, ax1), 1.0f);
    float ah  = __fadd_rn(__fsub_rn(ay2, ay1), 1.0f);
    float acx = __fadd_rn(ax1, __fmul_rn(0.5f, aw));
    float acy = __fadd_rn(ay1, __fmul_rn(0.5f, ah));

    int base = (4 * a) * HWPIX + pix;
    float dx = del[base];
    float dy = del[base + HWPIX];
    float dw = del[base + 2 * HWPIX];
    float dh = del[base + 3 * HWPIX];
    dw = fminf(fmaxf(dw, -10.0f), 10.0f);
    dh = fminf(fmaxf(dh, -10.0f), 10.0f);

    float pcx = __fadd_rn(__fmul_rn(dx, aw), acx);
    float pcy = __fadd_rn(__fmul_rn(dy, ah), acy);
    float pw  = __fmul_rn(expf(dw), aw);
    float ph  = __fmul_rn(expf(dh), ah);

    float hx = __fmul_rn(0.5f, pw);
    float hy = __fmul_rn(0.5f, ph);
    float x1 = fminf(fmaxf(__fsub_rn(pcx, hx), 0.0f), imW1);
    float y1 = fminf(fmaxf(__fsub_rn(pcy, hy), 0.0f), imH1);
    float x2 = fminf(fmaxf(__fsub_rn(__fadd_rn(pcx, hx), 1.0f), 0.0f), imW1);
    float y2 = fminf(fmaxf(__fsub_rn(__fadd_rn(pcy, hy), 1.0f), 0.0f), imH1);

    valid = (__fadd_rn(__fsub_rn(x2, x1), 1.0f) >= ms) &&
            (__fadd_rn(__fsub_rn(y2, y1), 1.0f) >= ms);
    return make_float4(x1, y1, x2, y2);
}

// ---------------- loose threshold over uniform bins (block 0) ----------------
__device__ __forceinline__ void loose_search(int target)
{
    __shared__ u32 co[1024];
    __shared__ int cth;
    __shared__ u32 cnxt;
    int t = threadIdx.x;
    u32 cur = g_histb[4 * t + 0] + g_histb[4 * t + 1]
            + g_histb[4 * t + 2] + g_histb[4 * t + 3];
    co[t] = cur;
    __syncthreads();
    for (int off = 1; off < 1024; off <<= 1) {
        u32 o = (t + off < 1024) ? co[t + off] : 0u;
        __syncthreads();
        cur += o;
        co[t] = cur;
        __syncthreads();
    }
    if (t == 0) cth = -1;
    __syncthreads();
    u32 nxt = (t < 1023) ? co[t + 1] : 0u;
    if (cur >= (u32)target && nxt < (u32)target) { cth = t; cnxt = nxt; }
    __syncthreads();
    if (t == 0) {
        int bin; u32 acc;
        if (cth < 0) { bin = 0; acc = co[0]; }
        else {
            acc = cnxt; bin = cth * 4;
            for (int b = 3; b >= 0; --b) {
                acc += g_histb[cth * 4 + b];
                if (acc >= (u32)target) { bin = cth * 4 + b; break; }
            }
        }
        while (acc > (u32)CAPR && bin < UBINS - 1) {
            u32 hb = g_histb[bin];
            if (acc - hb < (u32)PRE) break;
            acc -= hb; bin++;
        }
        g_Tloose = bin;
    }
}

// ---------------- candidate scan: decode + push valid, binLo <= ubin < binHi ----------------
__device__ __forceinline__ void scan_candidates(const float* __restrict__ fg,
                                                const float* __restrict__ del,
                                                const float4* __restrict__ anc,
                                                float imW1, float imH1, float ms,
                                                int binLo, int binHi,
                                                int gtid, int gs, int lane)
{
    for (int v4 = gtid; v4 < TOT / 4; v4 += gs) {
        int base = v4 * 4;
        float4 sc = *(const float4*)(fg + base);
        float s4[4] = { sc.x, sc.y, sc.z, sc.w };
#pragma unroll
        for (int k = 0; k < 4; ++k) {
            int bn = ubin(s4[k]);
            bool inband = (bn >= binLo) && (bn < binHi);
            bool keep = false;
            float4 bx;
            int item = base + k;
            if (inband) {
                int a   = item >> 16;
                int pix = item & 65535;
                bool valid;
                bx = decode_box(pix, a, del, anc, imW1, imH1, ms, valid);
                keep = valid;
            }
            u32 m = __ballot_sync(0xFFFFFFFFu, keep);
            if (keep) {
                int rank = __popc(m & ((1u << lane) - 1));
                int leader = __ffs(m) - 1;
                int bp = 0;
                if (lane == leader) bp = atomicAdd(&g_candcnt, __popc(m));
                bp = __shfl_sync(m, bp, leader);
                int a   = item >> 16;
                int pix = item & 65535;
                int ti  = pix * NA + a;
                int pos = bp + rank;
                if (pos < CAPBIG) {
                    u32 ob = obits(s4[k]);
                    g_cand[pos] = ((u64)ob << 32) | (u64)(0xFFFFFFFFu - (u32)ti);
                    g_boxstore[ti] = bx;
                }
            }
        }
    }
}

// ---------------- one IoU mask tile ----------------
__device__ __forceinline__ void iou_tile(int cB, int rb, int limit,
                                         float4* cb, float* ca, int tid)
{
    int j0 = cB * 64;
    __syncthreads();
    if (tid < 64) {
        int j = j0 + tid;
        if (j < limit) { cb[tid] = g_boxes[j]; ca[tid] = g_area[j]; }
        else           { cb[tid] = make_float4(0.f, 0.f, -1.f, -1.f); ca[tid] = 0.f; }
    }
    __syncthreads();
    int i = rb * NTHR + tid;
    if (i < limit) {
        u64 word = 0ull;
        int c0 = (i >= j0) ? (i - j0 + 1) : 0;
        int cmax = min(64, limit - j0);
        if (c0 < cmax) {
            float4 bi = g_boxes[i];
            float ai = g_area[i];
            for (int c = c0; c < cmax; ++c) {
                float4 bj = cb[c];
                float ix1 = fmaxf(bi.x, bj.x);
                float iy1 = fmaxf(bi.y, bj.y);
                float ix2 = fminf(bi.z, bj.z);
                float iy2 = fminf(bi.w, bj.w);
                float iw = fmaxf(__fadd_rn(__fsub_rn(ix2, ix1), 1.0f), 0.0f);
                float ih = fmaxf(__fadd_rn(__fsub_rn(iy2, iy1), 1.0f), 0.0f);
                float inter = __fmul_rn(iw, ih);
                float u = __fsub_rn(__fadd_rn(ai, ca[c]), inter);
                float t7  = __fmul_rn(NMS_T, u);
                float d   = __fsub_rn(inter, t7);
                float mar = __fmul_rn(2e-6f, u);
                bool sup;
                if (fabsf(d) <= mar) sup = (__fdiv_rn(inter, u) > NMS_T);
                else                 sup = (d > 0.0f);
                if (sup) word |= (1ull << c);
            }
        }
        g_mask[(size_t)i * WPITCH + cB] = word;
    }
}

// ---------------- sequential NMS scan (warp 0 of block 0) ----------------
__device__ __forceinline__ int nms_scan(float* __restrict__ out, int limit,
                                        int winMax, bool full, int lane)
{
    u64 S0 = 0ull, S1 = 0ull, S2 = 0ull;
    int nwin = min(winMax, (limit + 63) >> 6);

    u64 d_lo = (lane < limit) ? g_mask[(size_t)lane * WPITCH + 0] : 0ull;
    u64 d_hi = (lane + 32 < limit) ? g_mask[(size_t)(lane + 32) * WPITCH + 0] : 0ull;

    int kept = 0;
    for (int wi = 0; wi < nwin && kept < POST; ++wi) {
        u64 cur_lo = d_lo, cur_hi = d_hi;
        int wn = wi + 1;
        if (wn < nwin) {
            int r_lo = wn * 64 + lane;
            int r_hi = r_lo + 32;
            d_lo = (r_lo < limit) ? g_mask[(size_t)r_lo * WPITCH + wn] : 0ull;
            d_hi = (r_hi < limit) ? g_mask[(size_t)r_hi * WPITCH + wn] : 0ull;
        }

        int slot = wi >> 5, src = wi & 31;
        u64 mine = (slot == 0) ? S0 : ((slot == 1) ? S1 : S2);
        u64 w = __shfl_sync(0xFFFFFFFFu, mine, src);
        u64 alive = ~w;
        int bmax = min(64, limit - wi * 64);
        if (bmax < 64) alive &= (1ull << bmax) - 1ull;

        while (alive && kept < POST) {
            int b = __ffsll(alive) - 1;
            alive &= alive - 1ull;
            int i = wi * 64 + b;

            const float* bp = (const float*)&g_boxes[i];
            if (lane < 4)       out[kept * 5 + 1 + lane] = bp[lane];
            else if (lane == 4) out[kept * 5] = 0.0f;
            kept++;

            size_t base = (size_t)i * WPITCH;
            S0 |= g_mask[base + lane];
            if (full) {
                S1 |= g_mask[base + lane + 32];
                if (lane < 30) S2 |= g_mask[base + lane + 64];
            }

            u64 dwb = __shfl_sync(0xFFFFFFFFu, (b < 32) ? cur_lo : cur_hi, b & 31);
            alive &= ~dwb;
        }
    }
    return kept;
}

// ---------------- THE fused persistent kernel ----------------
__global__ void __launch_bounds__(NTHR, 1)
fused_proposal(const float* __restrict__ probs,
               const float* __restrict__ del,
               const float* __restrict__ img,
               const float* __restrict__ anchors,
               float* __restrict__ out)
{
    extern __shared__ u64 sk[];
    __shared__ float4 cb[64];
    __shared__ float  ca[64];
    __shared__ u32    pr[32 * 32];
    __shared__ int    sh_kept;
    __shared__ int    sh_ctrl;

    const int tid  = threadIdx.x;
    const int gtid = blockIdx.x * NTHR + tid;
    const int gs   = gridDim.x * NTHR;
    const int nb   = gridDim.x;
    const int lane = tid & 31;
    const int wrp  = tid >> 5;

    const float* fg = probs + NA * HWPIX;
    const float4* anc = (const float4*)anchors;
    float imH1 = __fsub_rn(img[0], 1.0f);
    float imW1 = __fsub_rn(img[1], 1.0f);
    float ms   = __fmul_rn(16.0f, img[2]);

    if (gtid == 0) *(volatile int*)&g_ctrl = 0;     // ordered by first gbar

    // ---- Pass A: speculative single-pass candidate selection ----
    scan_candidates(fg, del, anc, imW1, imH1, ms, T0BIN, UBINS, gtid, gs, lane);
    gbar();

    int NC = *(volatile int*)&g_candcnt;

    // ---- repair path (rare: speculative band too small / too large) ----
    if (NC < PRE || NC > CAPR) {
        // exact histogram, then re-select from scratch
        {
            u32* shh = (u32*)sk;
            for (int i = tid; i < UBINS; i += NTHR) shh[i] = 0u;
            __syncthreads();
            for (int v4 = gtid; v4 < TOT / 4; v4 += gs) {
                float4 sc = *(const float4*)(fg + v4 * 4);
                atomicAdd(&shh[ubin(sc.x)], 1u);
                atomicAdd(&shh[ubin(sc.y)], 1u);
                atomicAdd(&shh[ubin(sc.z)], 1u);
                atomicAdd(&shh[ubin(sc.w)], 1u);
            }
            __syncthreads();
            for (int i = tid; i < UBINS; i += NTHR) {
                u32 c = shh[i];
                if (c) atomicAdd(&g_histb[i], c);
            }
        }
        if (gtid == 0) g_candcnt = 0;
        gbar();
        if (blockIdx.x == 0) loose_search(LOOSE_TARGET);
        gbar();
        {
            int tl = g_Tloose;
            scan_candidates(fg, del, anc, imW1, imH1, ms, tl, UBINS, gtid, gs, lane);
            for (int i = gtid; i < UBINS; i += gs) g_histb[i] = 0u;   // reset for next replay
        }
        gbar();
        // extend band downward if still short of valid candidates
        for (int it = 0; it < 4; ++it) {
            int NCc = *(volatile int*)&g_candcnt;
            int tl  = *(volatile int*)&g_Tloose;
            if (NCc >= PRE || tl <= 0) break;
            int newb = tl - (64 << (2 * it));
            if (newb < 0) newb = 0;
            scan_candidates(fg, del, anc, imW1, imH1, ms, newb, tl, gtid, gs, lane);
            if (gtid == 0) g_Tloose = newb;
            gbar();
        }
        NC = *(volatile int*)&g_candcnt;
    }

    // ---- P4: rank-and-scatter (exact descending order) ----
    {
        int NCr = min(NC, CAPR);
        for (int i = tid; i < NCr; i += NTHR) sk[i] = g_cand[i];
        __syncthreads();
        int NG = (NCr + 31) >> 5;
        int CH = (NCr + 31) >> 5;
        for (int g = blockIdx.x; g < NG; g += nb) {
            int ci = g * 32 + lane;
            u64 mykey = (ci < NCr) ? sk[ci] : 0xFFFFFFFFFFFFFFFFull;
            int k0 = wrp * CH;
            int k1 = min(k0 + CH, NCr);
            u32 cnt = 0;
            for (int k = k0; k < k1; ++k)
                cnt += (sk[k] > mykey) ? 1u : 0u;
            pr[wrp * 32 + lane] = cnt;
            __syncthreads();
            if (wrp == 0) {
                u32 rank = 0;
#pragma unroll
                for (int ww = 0; ww < 32; ++ww) rank += pr[ww * 32 + lane];
                if (ci < NCr && rank < PRE) {
                    u32 ti = 0xFFFFFFFFu - (u32)(mykey & 0xFFFFFFFFull);
                    float4 bx = g_boxstore[ti];
                    g_boxes[rank] = bx;
                    g_area[rank] = __fmul_rn(__fadd_rn(__fsub_rn(bx.z, bx.x), 1.0f),
                                             __fadd_rn(__fsub_rn(bx.w, bx.y), 1.0f));
                }
            }
            __syncthreads();
        }
    }
    gbar();

    int limit = min(min(NC, CAPR), PRE);

    // ---- P10a: LAZY IoU tiles (cols < 32, rows < 2048) ----
    for (int tile = blockIdx.x; tile < LTILES; tile += nb) {
        int cB = tile & (LAZY_WIN - 1);
        int rb = tile >> 5;
        iou_tile(cB, rb, limit, cb, ca, tid);
    }
    gbar();

    // ---- P11: bounded scan on block 0; others poll ----
    if (blockIdx.x == 0) {
        if (tid < 32) {
            int kept = nms_scan(out, limit, LAZY_WIN, false, lane);
            if (lane == 0) sh_kept = kept;
        }
        __syncthreads();
        bool ok = (sh_kept >= POST) || (limit <= LAZY_ROWS);
        if (tid == 0) {
            __threadfence();
            *(volatile int*)&g_ctrl = ok ? 1 : 2;
        }
        __syncthreads();
        if (ok) {
            int kept = sh_kept;
            int rem = (POST - kept) * 5;
            for (int z = tid; z < rem; z += NTHR)
                out[kept * 5 + z] = 0.0f;
            if (tid == 0) g_candcnt = 0;
            return;
        }
    } else {
        if (tid == 0) {
            int c;
            while ((c = *(volatile int*)&g_ctrl) == 0) { }
            sh_ctrl = c;
        }
        __syncthreads();
        if (sh_ctrl == 1) return;
    }

    // ---- rare: compute remaining tiles, full rescan ----
    for (int tile = blockIdx.x; tile < NTILES; tile += nb) {
        int cB = tile % NWORDS;
        int rb = tile / NWORDS;
        if (cB < LAZY_WIN && rb < 2) continue;
        iou_tile(cB, rb, limit, cb, ca, tid);
    }
    gbar();

    if (blockIdx.x != 0) return;
    if (tid < 32) {
        int kept = nms_scan(out, limit, NWORDS, true, lane);
        int rem = (POST - kept) * 5;
        for (int z = lane; z < rem; z += 32)
            out[kept * 5 + z] = 0.0f;
        if (lane == 0) g_candcnt = 0;
    }
}

// ---------------- launch ----------------
extern "C" void kernel_launch(void* const* d_in, const int* in_sizes, int n_in,
                              void* d_out, int out_size)
{
    const float* probs   = (const float*)d_in[0];
    const float* del     = (const float*)d_in[1];
    const float* img     = (const float*)d_in[2];
    const float* anchors = (const float*)d_in[3];
    float* out = (float*)d_out;

    cudaFuncSetAttribute(fused_proposal,
                         cudaFuncAttributeMaxDynamicSharedMemorySize, DSMEM);
    int dev = 0;
    cudaGetDevice(&dev);
    int nsm = 0;
    cudaDeviceGetAttribute(&nsm, cudaDevAttrMultiProcessorCount, dev);
    if (nsm < 8) nsm = 8;

    fused_proposal<<<nsm, NTHR, DSMEM>>>(probs, del, img, anchors, out);
}

// round 14
// speedup vs baseline: 3.2605x; 1.3167x over previous
#include <cuda_runtime.h>
#include <cstdint>

typedef unsigned long long u64;
typedef unsigned int u32;

// ---------------- problem constants ----------------
#define NA 9
#define HWPIX 65536
#define TOT 589824
#define PRE 6000
#define POST 300
#define NMS_T 0.7f
#define NWORDS 94
#define WPITCH 96
#define CAPBIG 16384
#define CAPR 12288
#define LOOSE_TARGET 6500
#define UBINS 4096
#define T0BIN 4050              // speculative band: ~6620 expected items
#define NTHR 1024
#define DSMEM (CAPR * 8)
#define LAZY_WIN 16
#define LAZY_ROWS 1024
#define NTILES (NWORDS * 6)
#define LTILES LAZY_WIN         // 16 cols x 1 row-block of 1024

// ---------------- scratch ----------------
__device__ u32 g_barcnt;                 // monotonic across replays
__device__ u32 g_histb[UBINS];           // zero at entry; repair path re-zeroes after use
__device__ int g_Tloose;
__device__ int g_candcnt;
__device__ int g_ctrl;
__device__ u64 g_cand[CAPBIG];
__device__ float4 g_boxstore[TOT];
__device__ float4 g_boxes[PRE];
__device__ float  g_area[PRE];
__device__ u64 g_mask[(size_t)PRE * WPITCH];

// ---------------- software grid barrier ----------------
__device__ __forceinline__ void gbar()
{
    __syncthreads();
    if (threadIdx.x == 0) {
        __threadfence();
        u32 nb = gridDim.x;
        u32 my = atomicAdd(&g_barcnt, 1u) + 1u;
        u32 rem = my % nb;
        u32 tgt = rem ? my + (nb - rem) : my;
        while ((int)(*(volatile u32*)&g_barcnt - tgt) < 0) { }
        __threadfence();
    }
    __syncthreads();
}

__device__ __forceinline__ u32 obits(float score)
{
    u32 sb = __float_as_uint(score);
    return (sb & 0x80000000u) ? ~sb : (sb | 0x80000000u);
}

__device__ __forceinline__ int ubin(float s)
{
    int b = (int)__fmul_rn(s, 4096.0f);
    return max(0, min(UBINS - 1, b));
}

// ---------------- box decode (explicit RN: match XLA no-fma) ----------------
__device__ __forceinline__ float4 decode_box(int pix, int a,
                                             const float* __restrict__ del,
                                             const float4* __restrict__ anc,
                                             float imW1, float imH1, float ms,
                                             bool& valid)
{
    float sx = __fmul_rn((float)(pix & 255), 16.0f);
    float sy = __fmul_rn((float)(pix >> 8), 16.0f);
    float4 A = anc[a];
    float ax1 = __fadd_rn(A.x, sx);
    float ay1 = __fadd_rn(A.y, sy);
    float ax2 = __fadd_rn(A.z, sx);
    float ay2 = __fadd_rn(A.w, sy);
    float aw  = __fadd_rn(__fsub_rn(ax2, ax1), 1.0f);
    float ah  = __fadd_rn(__fsub_rn(ay2, ay1), 1.0f);
    float acx = __fadd_rn(ax1, __fmul_rn(0.5f, aw));
    float acy = __fadd_rn(ay1, __fmul_rn(0.5f, ah));

    int base = (4 * a) * HWPIX + pix;
    float dx = del[base];
    float dy = del[base + HWPIX];
    float dw = del[base + 2 * HWPIX];
    float dh = del[base + 3 * HWPIX];
    dw = fminf(fmaxf(dw, -10.0f), 10.0f);
    dh = fminf(fmaxf(dh, -10.0f), 10.0f);

    float pcx = __fadd_rn(__fmul_rn(dx, aw), acx);
    float pcy = __fadd_rn(__fmul_rn(dy, ah), acy);
    float pw  = __fmul_rn(expf(dw), aw);
    float ph  = __fmul_rn(expf(dh), ah);

    float hx = __fmul_rn(0.5f, pw);
    float hy = __fmul_rn(0.5f, ph);
    float x1 = fminf(fmaxf(__fsub_rn(pcx, hx), 0.0f), imW1);
    float y1 = fminf(fmaxf(__fsub_rn(pcy, hy), 0.0f), imH1);
    float x2 = fminf(fmaxf(__fsub_rn(__fadd_rn(pcx, hx), 1.0f), 0.0f), imW1);
    float y2 = fminf(fmaxf(__fsub_rn(__fadd_rn(pcy, hy), 1.0f), 0.0f), imH1);

    valid = (__fadd_rn(__fsub_rn(x2, x1), 1.0f) >= ms) &&
            (__fadd_rn(__fsub_rn(y2, y1), 1.0f) >= ms);
    return make_float4(x1, y1, x2, y2);
}

// ---------------- loose threshold over uniform bins (block 0) ----------------
__device__ __forceinline__ void loose_search(int target)
{
    __shared__ u32 co[1024];
    __shared__ int cth;
    __shared__ u32 cnxt;
    int t = threadIdx.x;
    u32 cur = g_histb[4 * t + 0] + g_histb[4 * t + 1]
            + g_histb[4 * t + 2] + g_histb[4 * t + 3];
    co[t] = cur;
    __syncthreads();
    for (int off = 1; off < 1024; off <<= 1) {
        u32 o = (t + off < 1024) ? co[t + off] : 0u;
        __syncthreads();
        cur += o;
        co[t] = cur;
        __syncthreads();
    }
    if (t == 0) cth = -1;
    __syncthreads();
    u32 nxt = (t < 1023) ? co[t + 1] : 0u;
    if (cur >= (u32)target && nxt < (u32)target) { cth = t; cnxt = nxt; }
    __syncthreads();
    if (t == 0) {
        int bin; u32 acc;
        if (cth < 0) { bin = 0; acc = co[0]; }
        else {
            acc = cnxt; bin = cth * 4;
            for (int b = 3; b >= 0; --b) {
                acc += g_histb[cth * 4 + b];
                if (acc >= (u32)target) { bin = cth * 4 + b; break; }
            }
        }
        while (acc > (u32)CAPR && bin < UBINS - 1) {
            u32 hb = g_histb[bin];
            if (acc - hb < (u32)PRE) break;
            acc -= hb; bin++;
        }
        g_Tloose = bin;
    }
}

// ---------------- candidate scan: decode + push valid, binLo <= ubin < binHi ----------------
__device__ __forceinline__ void scan_candidates(const float* __restrict__ fg,
                                                const float* __restrict__ del,
                                                const float4* __restrict__ anc,
                                                float imW1, float imH1, float ms,
                                                int binLo, int binHi,
                                                int gtid, int gs, int lane)
{
    for (int v4 = gtid; v4 < TOT / 4; v4 += gs) {
        int base = v4 * 4;
        float4 sc = *(const float4*)(fg + base);
        float s4[4] = { sc.x, sc.y, sc.z, sc.w };
#pragma unroll
        for (int k = 0; k < 4; ++k) {
            int bn = ubin(s4[k]);
            bool inband = (bn >= binLo) && (bn < binHi);
            bool keep = false;
            float4 bx;
            int item = base + k;
            if (inband) {
                int a   = item >> 16;
                int pix = item & 65535;
                bool valid;
                bx = decode_box(pix, a, del, anc, imW1, imH1, ms, valid);
                keep = valid;
            }
            u32 m = __ballot_sync(0xFFFFFFFFu, keep);
            if (keep) {
                int rank = __popc(m & ((1u << lane) - 1));
                int leader = __ffs(m) - 1;
                int bp = 0;
                if (lane == leader) bp = atomicAdd(&g_candcnt, __popc(m));
                bp = __shfl_sync(m, bp, leader);
                int a   = item >> 16;
                int pix = item & 65535;
                int ti  = pix * NA + a;
                int pos = bp + rank;
                if (pos < CAPBIG) {
                    u32 ob = obits(s4[k]);
                    g_cand[pos] = ((u64)ob << 32) | (u64)(0xFFFFFFFFu - (u32)ti);
                    g_boxstore[ti] = bx;
                }
            }
        }
    }
}

// ---------------- one IoU mask tile ----------------
__device__ __forceinline__ void iou_tile(int cB, int rb, int limit,
                                         float4* cb, float* ca, int tid)
{
    int j0 = cB * 64;
    __syncthreads();
    if (tid < 64) {
        int j = j0 + tid;
        if (j < limit) { cb[tid] = g_boxes[j]; ca[tid] = g_area[j]; }
        else           { cb[tid] = make_float4(0.f, 0.f, -1.f, -1.f); ca[tid] = 0.f; }
    }
    __syncthreads();
    int i = rb * NTHR + tid;
    if (i < limit) {
        u64 word = 0ull;
        int c0 = (i >= j0) ? (i - j0 + 1) : 0;
        int cmax = min(64, limit - j0);
        if (c0 < cmax) {
            float4 bi = g_boxes[i];
            float ai = g_area[i];
            for (int c = c0; c < cmax; ++c) {
                float4 bj = cb[c];
                float ix1 = fmaxf(bi.x, bj.x);
                float iy1 = fmaxf(bi.y, bj.y);
                float ix2 = fminf(bi.z, bj.z);
                float iy2 = fminf(bi.w, bj.w);
                float iw = fmaxf(__fadd_rn(__fsub_rn(ix2, ix1), 1.0f), 0.0f);
                float ih = fmaxf(__fadd_rn(__fsub_rn(iy2, iy1), 1.0f), 0.0f);
                float inter = __fmul_rn(iw, ih);
                float u = __fsub_rn(__fadd_rn(ai, ca[c]), inter);
                float t7  = __fmul_rn(NMS_T, u);
                float d   = __fsub_rn(inter, t7);
                float mar = __fmul_rn(2e-6f, u);
                bool sup;
                if (fabsf(d) <= mar) sup = (__fdiv_rn(inter, u) > NMS_T);
                else                 sup = (d > 0.0f);
                if (sup) word |= (1ull << c);
            }
        }
        g_mask[(size_t)i * WPITCH + cB] = word;
    }
}

// ---------------- sequential NMS scan (warp 0 of block 0) ----------------
// full=false: only S0 maintained (winMax<=32); row-OR loads guarded to lane<winMax
__device__ __forceinline__ int nms_scan(float* __restrict__ out, int limit,
                                        int winMax, bool full, int lane)
{
    u64 S0 = 0ull, S1 = 0ull, S2 = 0ull;
    int nwin = min(winMax, (limit + 63) >> 6);

    u64 d_lo = (lane < limit) ? g_mask[(size_t)lane * WPITCH + 0] : 0ull;
    u64 d_hi = (lane + 32 < limit) ? g_mask[(size_t)(lane + 32) * WPITCH + 0] : 0ull;

    int kept = 0;
    for (int wi = 0; wi < nwin && kept < POST; ++wi) {
        u64 cur_lo = d_lo, cur_hi = d_hi;
        int wn = wi + 1;
        if (wn < nwin) {
            int r_lo = wn * 64 + lane;
            int r_hi = r_lo + 32;
            d_lo = (r_lo < limit) ? g_mask[(size_t)r_lo * WPITCH + wn] : 0ull;
            d_hi = (r_hi < limit) ? g_mask[(size_t)r_hi * WPITCH + wn] : 0ull;
        }

        int slot = wi >> 5, src = wi & 31;
        u64 mine = (slot == 0) ? S0 : ((slot == 1) ? S1 : S2);
        u64 w = __shfl_sync(0xFFFFFFFFu, mine, src);
        u64 alive = ~w;
        int bmax = min(64, limit - wi * 64);
        if (bmax < 64) alive &= (1ull << bmax) - 1ull;

        // intra-window suppression test: does any alive row hit any alive bit?
        u64 t = 0ull;
        if ((alive >> lane) & 1ull)        t  = cur_lo & alive;
        if ((alive >> (lane + 32)) & 1ull) t |= cur_hi & alive;
        bool intra = __any_sync(0xFFFFFFFFu, t != 0ull);

        if (!intra) {
            // fast path: all alive bits are kept; no shuffle in the loop
            u64 a = alive;
            while (a && kept < POST) {
                int b = __ffsll(a) - 1;
                a &= a - 1ull;
                int i = wi * 64 + b;

                const float* bp = (const float*)&g_boxes[i];
                if (lane < 4)       out[kept * 5 + 1 + lane] = bp[lane];
                else if (lane == 4) out[kept * 5] = 0.0f;
                kept++;

                size_t base = (size_t)i * WPITCH;
                if (full) {
                    S0 |= g_mask[base + lane];
                    S1 |= g_mask[base + lane + 32];
                    if (lane < 30) S2 |= g_mask[base + lane + 64];
                } else if (lane < winMax) {
                    S0 |= g_mask[base + lane];
                }
            }
        } else {
            // exact path with per-keep diag shuffle
            while (alive && kept < POST) {
                int b = __ffsll(alive) - 1;
                alive &= alive - 1ull;
                int i = wi * 64 + b;

                const float* bp = (const float*)&g_boxes[i];
                if (lane < 4)       out[kept * 5 + 1 + lane] = bp[lane];
                else if (lane == 4) out[kept * 5] = 0.0f;
                kept++;

                size_t base = (size_t)i * WPITCH;
                if (full) {
                    S0 |= g_mask[base + lane];
                    S1 |= g_mask[base + lane + 32];
                    if (lane < 30) S2 |= g_mask[base + lane + 64];
                } else if (lane < winMax) {
                    S0 |= g_mask[base + lane];
                }

                u64 dwb = __shfl_sync(0xFFFFFFFFu, (b < 32) ? cur_lo : cur_hi, b & 31);
                alive &= ~dwb;
            }
        }
    }
    return kept;
}

// ---------------- THE fused persistent kernel ----------------
__global__ void __launch_bounds__(NTHR, 1)
fused_proposal(const float* __restrict__ probs,
               const float* __restrict__ del,
               const float* __restrict__ img,
               const float* __restrict__ anchors,
               float* __restrict__ out)
{
    extern __shared__ u64 sk[];
    __shared__ float4 cb[64];
    __shared__ float  ca[64];
    __shared__ u32    pr[32 * 32];
    __shared__ int    sh_kept;
    __shared__ int    sh_ctrl;

    const int tid  = threadIdx.x;
    const int gtid = blockIdx.x * NTHR + tid;
    const int gs   = gridDim.x * NTHR;
    const int nb   = gridDim.x;
    const int lane = tid & 31;
    const int wrp  = tid >> 5;

    const float* fg = probs + NA * HWPIX;
    const float4* anc = (const float4*)anchors;
    float imH1 = __fsub_rn(img[0], 1.0f);
    float imW1 = __fsub_rn(img[1], 1.0f);
    float ms   = __fmul_rn(16.0f, img[2]);

    if (gtid == 0) *(volatile int*)&g_ctrl = 0;     // ordered by first gbar

    // ---- Pass A: speculative single-pass candidate selection ----
    scan_candidates(fg, del, anc, imW1, imH1, ms, T0BIN, UBINS, gtid, gs, lane);
    gbar();

    int NC = *(volatile int*)&g_candcnt;

    // ---- repair path (rare: speculative band too small / too large) ----
    if (NC < PRE || NC > CAPR) {
        {
            u32* shh = (u32*)sk;
            for (int i = tid; i < UBINS; i += NTHR) shh[i] = 0u;
            __syncthreads();
            for (int v4 = gtid; v4 < TOT / 4; v4 += gs) {
                float4 sc = *(const float4*)(fg + v4 * 4);
                atomicAdd(&shh[ubin(sc.x)], 1u);
                atomicAdd(&shh[ubin(sc.y)], 1u);
                atomicAdd(&shh[ubin(sc.z)], 1u);
                atomicAdd(&shh[ubin(sc.w)], 1u);
            }
            __syncthreads();
            for (int i = tid; i < UBINS; i += NTHR) {
                u32 c = shh[i];
                if (c) atomicAdd(&g_histb[i], c);
            }
        }
        if (gtid == 0) g_candcnt = 0;
        gbar();
        if (blockIdx.x == 0) loose_search(LOOSE_TARGET);
        gbar();
        {
            int tl = g_Tloose;
            scan_candidates(fg, del, anc, imW1, imH1, ms, tl, UBINS, gtid, gs, lane);
            for (int i = gtid; i < UBINS; i += gs) g_histb[i] = 0u;
        }
        gbar();
        for (int it = 0; it < 4; ++it) {
            int NCc = *(volatile int*)&g_candcnt;
            int tl  = *(volatile int*)&g_Tloose;
            if (NCc >= PRE || tl <= 0) break;
            int newb = tl - (64 << (2 * it));
            if (newb < 0) newb = 0;
            scan_candidates(fg, del, anc, imW1, imH1, ms, newb, tl, gtid, gs, lane);
            if (gtid == 0) g_Tloose = newb;
            gbar();
        }
        NC = *(volatile int*)&g_candcnt;
    }

    // ---- P4: rank-and-scatter (exact descending order) ----
    {
        int NCr = min(NC, CAPR);
        for (int i = tid; i < NCr; i += NTHR) sk[i] = g_cand[i];
        __syncthreads();
        int NG = (NCr + 31) >> 5;
        int CH = (NCr + 31) >> 5;
        for (int g = blockIdx.x; g < NG; g += nb) {
            int ci = g * 32 + lane;
            u64 mykey = (ci < NCr) ? sk[ci] : 0xFFFFFFFFFFFFFFFFull;
            int k0 = wrp * CH;
            int k1 = min(k0 + CH, NCr);
            u32 cnt = 0;
            for (int k = k0; k < k1; ++k)
                cnt += (sk[k] > mykey) ? 1u : 0u;
            pr[wrp * 32 + lane] = cnt;
            __syncthreads();
            if (wrp == 0) {
                u32 rank = 0;
#pragma unroll
                for (int ww = 0; ww < 32; ++ww) rank += pr[ww * 32 + lane];
                if (ci < NCr && rank < PRE) {
                    u32 ti = 0xFFFFFFFFu - (u32)(mykey & 0xFFFFFFFFull);
                    float4 bx = g_boxstore[ti];
                    g_boxes[rank] = bx;
                    g_area[rank] = __fmul_rn(__fadd_rn(__fsub_rn(bx.z, bx.x), 1.0f),
                                             __fadd_rn(__fsub_rn(bx.w, bx.y), 1.0f));
                }
            }
            __syncthreads();
        }
    }
    gbar();

    int limit = min(min(NC, CAPR), PRE);

    // ---- P10a: LAZY IoU tiles (cols < LAZY_WIN, rows < LAZY_ROWS) ----
    for (int tile = blockIdx.x; tile < LTILES; tile += nb) {
        iou_tile(tile, 0, limit, cb, ca, tid);
    }
    gbar();

    // ---- P11: bounded scan on block 0; others poll ----
    if (blockIdx.x == 0) {
        if (tid < 32) {
            int kept = nms_scan(out, limit, LAZY_WIN, false, lane);
            if (lane == 0) sh_kept = kept;
        }
        __syncthreads();
        bool ok = (sh_kept >= POST) || (limit <= LAZY_ROWS);
        if (tid == 0) {
            __threadfence();
            *(volatile int*)&g_ctrl = ok ? 1 : 2;
        }
        __syncthreads();
        if (ok) {
            int kept = sh_kept;
            int rem = (POST - kept) * 5;
            for (int z = tid; z < rem; z += NTHR)
                out[kept * 5 + z] = 0.0f;
            if (tid == 0) g_candcnt = 0;
            return;
        }
    } else {
        if (tid == 0) {
            int c;
            while ((c = *(volatile int*)&g_ctrl) == 0) { }
            sh_ctrl = c;
        }
        __syncthreads();
        if (sh_ctrl == 1) return;
    }

    // ---- rare: compute remaining tiles, full rescan ----
    for (int tile = blockIdx.x; tile < NTILES; tile += nb) {
        int cB = tile % NWORDS;
        int rb = tile / NWORDS;
        if (cB < LAZY_WIN && rb == 0) continue;      // already done
        iou_tile(cB, rb, limit, cb, ca, tid);
    }
    gbar();

    if (blockIdx.x != 0) return;
    if (tid < 32) {
        int kept = nms_scan(out, limit, NWORDS, true, lane);
        int rem = (POST - kept) * 5;
        for (int z = lane; z < rem; z += 32)
            out[kept * 5 + z] = 0.0f;
        if (lane == 0) g_candcnt = 0;
    }
}

// ---------------- launch ----------------
extern "C" void kernel_launch(void* const* d_in, const int* in_sizes, int n_in,
                              void* d_out, int out_size)
{
    const float* probs   = (const float*)d_in[0];
    const float* del     = (const float*)d_in[1];
    const float* img     = (const float*)d_in[2];
    const float* anchors = (const float*)d_in[3];
    float* out = (float*)d_out;

    cudaFuncSetAttribute(fused_proposal,
                         cudaFuncAttributeMaxDynamicSharedMemorySize, DSMEM);
    int dev = 0;
    cudaGetDevice(&dev);
    int nsm = 0;
    cudaDeviceGetAttribute(&nsm, cudaDevAttrMultiProcessorCount, dev);
    if (nsm < 8) nsm = 8;

    fused_proposal<<<nsm, NTHR, DSMEM>>>(probs, del, img, anchors, out);
}

// round 15
// speedup vs baseline: 4.0008x; 1.2271x over previous
#include <cuda_runtime.h>
#include <cstdint>

typedef unsigned long long u64;
typedef unsigned int u32;

// ---------------- problem constants ----------------
#define NA 9
#define HWPIX 65536
#define TOT 589824
#define PRE 6000
#define POST 300
#define NMS_T 0.7f
#define NWORDS 94
#define WPITCH 96
#define CAPBIG 16384
#define CAPR 12288
#define LOOSE_TARGET 6500
#define UBINS 4096
#define T0BIN 4050              // speculative band: ~6620 expected items
#define NTHR 1024
#define DSMEM (CAPR * 8)
#define LAZY_WIN 16
#define LAZY_ROWS 1024
#define NTILES (NWORDS * 6)
#define LTILES LAZY_WIN         // 16 cols x 1 row-block of 1024

// ---------------- scratch ----------------
__device__ u32 g_barcnt;                 // monotonic across replays
__device__ u32 g_histb[UBINS];           // zero at entry; repair path re-zeroes after use
__device__ int g_Tloose;
__device__ int g_candcnt;
__device__ int g_ctrl;
__device__ u64 g_cand[CAPBIG];
__device__ float4 g_boxstore[TOT];
__device__ float4 g_boxes[PRE];
__device__ float  g_area[PRE];
__device__ u64 g_mask[(size_t)PRE * WPITCH];

// ---------------- software grid barrier ----------------
__device__ __forceinline__ void gbar()
{
    __syncthreads();
    if (threadIdx.x == 0) {
        __threadfence();
        u32 nb = gridDim.x;
        u32 my = atomicAdd(&g_barcnt, 1u) + 1u;
        u32 rem = my % nb;
        u32 tgt = rem ? my + (nb - rem) : my;
        while ((int)(*(volatile u32*)&g_barcnt - tgt) < 0) { }
        __threadfence();
    }
    __syncthreads();
}

__device__ __forceinline__ u32 obits(float score)
{
    u32 sb = __float_as_uint(score);
    return (sb & 0x80000000u) ? ~sb : (sb | 0x80000000u);
}

__device__ __forceinline__ int ubin(float s)
{
    int b = (int)__fmul_rn(s, 4096.0f);
    return max(0, min(UBINS - 1, b));
}

// ---------------- box decode (explicit RN: match XLA no-fma) ----------------
__device__ __forceinline__ float4 decode_box(int pix, int a,
                                             const float* __restrict__ del,
                                             const float4* __restrict__ anc,
                                             float imW1, float imH1, float ms,
                                             bool& valid)
{
    float sx = __fmul_rn((float)(pix & 255), 16.0f);
    float sy = __fmul_rn((float)(pix >> 8), 16.0f);
    float4 A = anc[a];
    float ax1 = __fadd_rn(A.x, sx);
    float ay1 = __fadd_rn(A.y, sy);
    float ax2 = __fadd_rn(A.z, sx);
    float ay2 = __fadd_rn(A.w, sy);
    float aw  = __fadd_rn(__fsub_rn(ax2, ax1), 1.0f);
    float ah  = __fadd_rn(__fsub_rn(ay2, ay1), 1.0f);
    float acx = __fadd_rn(ax1, __fmul_rn(0.5f, aw));
    float acy = __fadd_rn(ay1, __fmul_rn(0.5f, ah));

    int base = (4 * a) * HWPIX + pix;
    float dx = del[base];
    float dy = del[base + HWPIX];
    float dw = del[base + 2 * HWPIX];
    float dh = del[base + 3 * HWPIX];
    dw = fminf(fmaxf(dw, -10.0f), 10.0f);
    dh = fminf(fmaxf(dh, -10.0f), 10.0f);

    float pcx = __fadd_rn(__fmul_rn(dx, aw), acx);
    float pcy = __fadd_rn(__fmul_rn(dy, ah), acy);
    float pw  = __fmul_rn(expf(dw), aw);
    float ph  = __fmul_rn(expf(dh), ah);

    float hx = __fmul_rn(0.5f, pw);
    float hy = __fmul_rn(0.5f, ph);
    float x1 = fminf(fmaxf(__fsub_rn(pcx, hx), 0.0f), imW1);
    float y1 = fminf(fmaxf(__fsub_rn(pcy, hy), 0.0f), imH1);
    float x2 = fminf(fmaxf(__fsub_rn(__fadd_rn(pcx, hx), 1.0f), 0.0f), imW1);
    float y2 = fminf(fmaxf(__fsub_rn(__fadd_rn(pcy, hy), 1.0f), 0.0f), imH1);

    valid = (__fadd_rn(__fsub_rn(x2, x1), 1.0f) >= ms) &&
            (__fadd_rn(__fsub_rn(y2, y1), 1.0f) >= ms);
    return make_float4(x1, y1, x2, y2);
}

// ---------------- loose threshold over uniform bins (block 0) ----------------
__device__ __forceinline__ void loose_search(int target)
{
    __shared__ u32 co[1024];
    __shared__ int cth;
    __shared__ u32 cnxt;
    int t = threadIdx.x;
    u32 cur = g_histb[4 * t + 0] + g_histb[4 * t + 1]
            + g_histb[4 * t + 2] + g_histb[4 * t + 3];
    co[t] = cur;
    __syncthreads();
    for (int off = 1; off < 1024; off <<= 1) {
        u32 o = (t + off < 1024) ? co[t + off] : 0u;
        __syncthreads();
        cur += o;
        co[t] = cur;
        __syncthreads();
    }
    if (t == 0) cth = -1;
    __syncthreads();
    u32 nxt = (t < 1023) ? co[t + 1] : 0u;
    if (cur >= (u32)target && nxt < (u32)target) { cth = t; cnxt = nxt; }
    __syncthreads();
    if (t == 0) {
        int bin; u32 acc;
        if (cth < 0) { bin = 0; acc = co[0]; }
        else {
            acc = cnxt; bin = cth * 4;
            for (int b = 3; b >= 0; --b) {
                acc += g_histb[cth * 4 + b];
                if (acc >= (u32)target) { bin = cth * 4 + b; break; }
            }
        }
        while (acc > (u32)CAPR && bin < UBINS - 1) {
            u32 hb = g_histb[bin];
            if (acc - hb < (u32)PRE) break;
            acc -= hb; bin++;
        }
        g_Tloose = bin;
    }
}

// ---------------- candidate scan: decode + push valid, binLo <= ubin < binHi ----------------
// order in g_cand is irrelevant (rank-and-scatter sorts by key) -> direct atomics
__device__ __forceinline__ void scan_candidates(const float* __restrict__ fg,
                                                const float* __restrict__ del,
                                                const float4* __restrict__ anc,
                                                float imW1, float imH1, float ms,
                                                int binLo, int binHi,
                                                int gtid, int gs)
{
    for (int v4 = gtid; v4 < TOT / 4; v4 += gs) {
        int base = v4 * 4;
        float4 sc = *(const float4*)(fg + base);
        float s4[4] = { sc.x, sc.y, sc.z, sc.w };
#pragma unroll
        for (int k = 0; k < 4; ++k) {
            int bn = ubin(s4[k]);
            if (bn >= binLo && bn < binHi) {
                int item = base + k;
                int a   = item >> 16;
                int pix = item & 65535;
                bool valid;
                float4 bx = decode_box(pix, a, del, anc, imW1, imH1, ms, valid);
                if (valid) {
                    int pos = atomicAdd(&g_candcnt, 1);
                    if (pos < CAPBIG) {
                        u32 ob = obits(s4[k]);
                        int ti = pix * NA + a;
                        g_cand[pos] = ((u64)ob << 32) | (u64)(0xFFFFFFFFu - (u32)ti);
                        g_boxstore[ti] = bx;
                    }
                }
            }
        }
    }
}

// ---------------- one IoU mask tile ----------------
__device__ __forceinline__ void iou_tile(int cB, int rb, int limit,
                                         float4* cb, float* ca, int tid)
{
    int j0 = cB * 64;
    __syncthreads();
    if (tid < 64) {
        int j = j0 + tid;
        if (j < limit) { cb[tid] = g_boxes[j]; ca[tid] = g_area[j]; }
        else           { cb[tid] = make_float4(0.f, 0.f, -1.f, -1.f); ca[tid] = 0.f; }
    }
    __syncthreads();
    int i = rb * NTHR + tid;
    if (i < limit) {
        u64 word = 0ull;
        int c0 = (i >= j0) ? (i - j0 + 1) : 0;
        int cmax = min(64, limit - j0);
        if (c0 < cmax) {
            float4 bi = g_boxes[i];
            float ai = g_area[i];
            for (int c = c0; c < cmax; ++c) {
                float4 bj = cb[c];
                float ix1 = fmaxf(bi.x, bj.x);
                float iy1 = fmaxf(bi.y, bj.y);
                float ix2 = fminf(bi.z, bj.z);
                float iy2 = fminf(bi.w, bj.w);
                float iw = fmaxf(__fadd_rn(__fsub_rn(ix2, ix1), 1.0f), 0.0f);
                float ih = fmaxf(__fadd_rn(__fsub_rn(iy2, iy1), 1.0f), 0.0f);
                float inter = __fmul_rn(iw, ih);
                float u = __fsub_rn(__fadd_rn(ai, ca[c]), inter);
                float t7  = __fmul_rn(NMS_T, u);
                float d   = __fsub_rn(inter, t7);
                float mar = __fmul_rn(2e-6f, u);
                bool sup;
                if (fabsf(d) <= mar) sup = (__fdiv_rn(inter, u) > NMS_T);
                else                 sup = (d > 0.0f);
                if (sup) word |= (1ull << c);
            }
        }
        g_mask[(size_t)i * WPITCH + cB] = word;
    }
}

// ---------------- sequential NMS scan (warp 0 of block 0) ----------------
// full=false: only S0 maintained (winMax<=32); row-OR loads guarded to lane<winMax
__device__ __forceinline__ int nms_scan(float* __restrict__ out, int limit,
                                        int winMax, bool full, int lane)
{
    u64 S0 = 0ull, S1 = 0ull, S2 = 0ull;
    int nwin = min(winMax, (limit + 63) >> 6);

    u64 d_lo = (lane < limit) ? g_mask[(size_t)lane * WPITCH + 0] : 0ull;
    u64 d_hi = (lane + 32 < limit) ? g_mask[(size_t)(lane + 32) * WPITCH + 0] : 0ull;

    int kept = 0;
    for (int wi = 0; wi < nwin && kept < POST; ++wi) {
        u64 cur_lo = d_lo, cur_hi = d_hi;
        int wn = wi + 1;
        if (wn < nwin) {
            int r_lo = wn * 64 + lane;
            int r_hi = r_lo + 32;
            d_lo = (r_lo < limit) ? g_mask[(size_t)r_lo * WPITCH + wn] : 0ull;
            d_hi = (r_hi < limit) ? g_mask[(size_t)r_hi * WPITCH + wn] : 0ull;
        }

        int slot = wi >> 5, src = wi & 31;
        u64 mine = (slot == 0) ? S0 : ((slot == 1) ? S1 : S2);
        u64 w = __shfl_sync(0xFFFFFFFFu, mine, src);
        u64 alive = ~w;
        int bmax = min(64, limit - wi * 64);
        if (bmax < 64) alive &= (1ull << bmax) - 1ull;

        // intra-window suppression test: does any alive row hit any alive bit?
        u64 t = 0ull;
        if ((alive >> lane) & 1ull)        t  = cur_lo & alive;
        if ((alive >> (lane + 32)) & 1ull) t |= cur_hi & alive;
        bool intra = __any_sync(0xFFFFFFFFu, t != 0ull);

        if (!intra) {
            // fast path: every alive bit is kept. Parallelize across lanes.
            u64 a = alive;
            int cnt = __popcll(a);
            int take = min(cnt, POST - kept);
            u32 alo = (u32)a, ahi = (u32)(a >> 32);
            int nlo = __popc(alo);

            // output writes: lane handles the (r+lane)-th kept bit
            for (int r = 0; r < take; r += 32) {
                int l = r + lane;
                if (l < take) {
                    int b = (l < nlo) ? (int)__fns(alo, 0, l + 1)
                                      : 32 + (int)__fns(ahi, 0, l + 1 - nlo);
                    float4 bx = g_boxes[wi * 64 + b];
                    float* op = out + (size_t)(kept + l) * 5;
                    op[0] = 0.0f; op[1] = bx.x; op[2] = bx.y;
                    op[3] = bx.z; op[4] = bx.w;
                }
            }

            // S-OR over the kept rows (tight loop, independent loads)
            u64 aa = a;
            for (int l = 0; l < take; ++l) {
                int b = __ffsll(aa) - 1;
                aa &= aa - 1ull;
                size_t base = (size_t)(wi * 64 + b) * WPITCH;
                if (full) {
                    S0 |= g_mask[base + lane];
                    S1 |= g_mask[base + lane + 32];
                    if (lane < 30) S2 |= g_mask[base + lane + 64];
                } else if (lane < winMax) {
                    S0 |= g_mask[base + lane];
                }
            }
            kept += take;
        } else {
            // exact path with per-keep diag shuffle
            while (alive && kept < POST) {
                int b = __ffsll(alive) - 1;
                alive &= alive - 1ull;
                int i = wi * 64 + b;

                const float* bp = (const float*)&g_boxes[i];
                if (lane < 4)       out[kept * 5 + 1 + lane] = bp[lane];
                else if (lane == 4) out[kept * 5] = 0.0f;
                kept++;

                size_t base = (size_t)i * WPITCH;
                if (full) {
                    S0 |= g_mask[base + lane];
                    S1 |= g_mask[base + lane + 32];
                    if (lane < 30) S2 |= g_mask[base + lane + 64];
                } else if (lane < winMax) {
                    S0 |= g_mask[base + lane];
                }

                u64 dwb = __shfl_sync(0xFFFFFFFFu, (b < 32) ? cur_lo : cur_hi, b & 31);
                alive &= ~dwb;
            }
        }
    }
    return kept;
}

// ---------------- THE fused persistent kernel ----------------
__global__ void __launch_bounds__(NTHR, 1)
fused_proposal(const float* __restrict__ probs,
               const float* __restrict__ del,
               const float* __restrict__ img,
               const float* __restrict__ anchors,
               float* __restrict__ out)
{
    extern __shared__ u64 sk[];
    __shared__ float4 cb[64];
    __shared__ float  ca[64];
    __shared__ u32    pr[32 * 32];
    __shared__ int    sh_kept;
    __shared__ int    sh_ctrl;

    const int tid  = threadIdx.x;
    const int gtid = blockIdx.x * NTHR + tid;
    const int gs   = gridDim.x * NTHR;
    const int nb   = gridDim.x;
    const int lane = tid & 31;
    const int wrp  = tid >> 5;

    const float* fg = probs + NA * HWPIX;
    const float4* anc = (const float4*)anchors;
    float imH1 = __fsub_rn(img[0], 1.0f);
    float imW1 = __fsub_rn(img[1], 1.0f);
    float ms   = __fmul_rn(16.0f, img[2]);

    if (gtid == 0) *(volatile int*)&g_ctrl = 0;     // ordered by first gbar

    // ---- Pass A: speculative single-pass candidate selection ----
    scan_candidates(fg, del, anc, imW1, imH1, ms, T0BIN, UBINS, gtid, gs);
    gbar();

    int NC = *(volatile int*)&g_candcnt;

    // ---- repair path (rare: speculative band too small / too large) ----
    if (NC < PRE || NC > CAPR) {
        {
            u32* shh = (u32*)sk;
            for (int i = tid; i < UBINS; i += NTHR) shh[i] = 0u;
            __syncthreads();
            for (int v4 = gtid; v4 < TOT / 4; v4 += gs) {
                float4 sc = *(const float4*)(fg + v4 * 4);
                atomicAdd(&shh[ubin(sc.x)], 1u);
                atomicAdd(&shh[ubin(sc.y)], 1u);
                atomicAdd(&shh[ubin(sc.z)], 1u);
                atomicAdd(&shh[ubin(sc.w)], 1u);
            }
            __syncthreads();
            for (int i = tid; i < UBINS; i += NTHR) {
                u32 c = shh[i];
                if (c) atomicAdd(&g_histb[i], c);
            }
        }
        if (gtid == 0) g_candcnt = 0;
        gbar();
        if (blockIdx.x == 0) loose_search(LOOSE_TARGET);
        gbar();
        {
            int tl = g_Tloose;
            scan_candidates(fg, del, anc, imW1, imH1, ms, tl, UBINS, gtid, gs);
            for (int i = gtid; i < UBINS; i += gs) g_histb[i] = 0u;
        }
        gbar();
        for (int it = 0; it < 4; ++it) {
            int NCc = *(volatile int*)&g_candcnt;
            int tl  = *(volatile int*)&g_Tloose;
            if (NCc >= PRE || tl <= 0) break;
            int newb = tl - (64 << (2 * it));
            if (newb < 0) newb = 0;
            scan_candidates(fg, del, anc, imW1, imH1, ms, newb, tl, gtid, gs);
            if (gtid == 0) g_Tloose = newb;
            gbar();
        }
        NC = *(volatile int*)&g_candcnt;
    }

    // ---- P4: rank-and-scatter (exact descending order) ----
    {
        int NCr = min(NC, CAPR);
        for (int i = tid; i < NCr; i += NTHR) sk[i] = g_cand[i];
        __syncthreads();
        int NG = (NCr + 31) >> 5;
        int CH = (NCr + 31) >> 5;
        for (int g = blockIdx.x; g < NG; g += nb) {
            int ci = g * 32 + lane;
            u64 mykey = (ci < NCr) ? sk[ci] : 0xFFFFFFFFFFFFFFFFull;
            int k0 = wrp * CH;
            int k1 = min(k0 + CH, NCr);
            u32 cnt = 0;
            for (int k = k0; k < k1; ++k)
                cnt += (sk[k] > mykey) ? 1u : 0u;
            pr[wrp * 32 + lane] = cnt;
            __syncthreads();
            if (wrp == 0) {
                u32 rank = 0;
#pragma unroll
                for (int ww = 0; ww < 32; ++ww) rank += pr[ww * 32 + lane];
                if (ci < NCr && rank < PRE) {
                    u32 ti = 0xFFFFFFFFu - (u32)(mykey & 0xFFFFFFFFull);
                    float4 bx = g_boxstore[ti];
                    g_boxes[rank] = bx;
                    g_area[rank] = __fmul_rn(__fadd_rn(__fsub_rn(bx.z, bx.x), 1.0f),
                                             __fadd_rn(__fsub_rn(bx.w, bx.y), 1.0f));
                }
            }
            __syncthreads();
        }
    }
    gbar();

    int limit = min(min(NC, CAPR), PRE);

    // ---- P10a: LAZY IoU tiles (cols < LAZY_WIN, rows < LAZY_ROWS) ----
    for (int tile = blockIdx.x; tile < LTILES; tile += nb) {
        iou_tile(tile, 0, limit, cb, ca, tid);
    }
    gbar();

    // ---- P11: bounded scan on block 0; others poll ----
    if (blockIdx.x == 0) {
        if (tid < 32) {
            int kept = nms_scan(out, limit, LAZY_WIN, false, lane);
            if (lane == 0) sh_kept = kept;
        }
        __syncthreads();
        bool ok = (sh_kept >= POST) || (limit <= LAZY_ROWS);
        if (tid == 0) {
            __threadfence();
            *(volatile int*)&g_ctrl = ok ? 1 : 2;
        }
        __syncthreads();
        if (ok) {
            int kept = sh_kept;
            int rem = (POST - kept) * 5;
            for (int z = tid; z < rem; z += NTHR)
                out[kept * 5 + z] = 0.0f;
            if (tid == 0) g_candcnt = 0;
            return;
        }
    } else {
        if (tid == 0) {
            int c;
            while ((c = *(volatile int*)&g_ctrl) == 0) { }
            sh_ctrl = c;
        }
        __syncthreads();
        if (sh_ctrl == 1) return;
    }

    // ---- rare: compute remaining tiles, full rescan ----
    for (int tile = blockIdx.x; tile < NTILES; tile += nb) {
        int cB = tile % NWORDS;
        int rb = tile / NWORDS;
        if (cB < LAZY_WIN && rb == 0) continue;      // already done
        iou_tile(cB, rb, limit, cb, ca, tid);
    }
    gbar();

    if (blockIdx.x != 0) return;
    if (tid < 32) {
        int kept = nms_scan(out, limit, NWORDS, true, lane);
        int rem = (POST - kept) * 5;
        for (int z = lane; z < rem; z += 32)
            out[kept * 5 + z] = 0.0f;
        if (lane == 0) g_candcnt = 0;
    }
}

// ---------------- launch ----------------
extern "C" void kernel_launch(void* const* d_in, const int* in_sizes, int n_in,
                              void* d_out, int out_size)
{
    const float* probs   = (const float*)d_in[0];
    const float* del     = (const float*)d_in[1];
    const float* img     = (const float*)d_in[2];
    const float* anchors = (const float*)d_in[3];
    float* out = (float*)d_out;

    cudaFuncSetAttribute(fused_proposal,
                         cudaFuncAttributeMaxDynamicSharedMemorySize, DSMEM);
    int dev = 0;
    cudaGetDevice(&dev);
    int nsm = 0;
    cudaDeviceGetAttribute(&nsm, cudaDevAttrMultiProcessorCount, dev);
    if (nsm < 8) nsm = 8;

    fused_proposal<<<nsm, NTHR, DSMEM>>>(probs, del, img, anchors, out);
}